// round 12
// baseline (speedup 1.0000x reference)
#include <cuda_runtime.h>
#include <cuda_bf16.h>
#include <math.h>

// Fixed problem shapes
#define BB 256   // batch
#define TT 512   // encoder sequence length
#define HH 256   // hidden size
#define GG 1024  // 4*H gate rows

typedef unsigned long long u64;

// ---------------------------------------------------------------------------
// f32x2 packed-math helpers (bitwise identical to scalar FFMA per lane)
// ---------------------------------------------------------------------------
__device__ __forceinline__ u64 pk2(float lo, float hi) {
    u64 r; asm("mov.b64 %0, {%1, %2};" : "=l"(r) : "f"(lo), "f"(hi)); return r;
}
__device__ __forceinline__ void fma2(u64& d, u64 a, u64 b) {
    asm("fma.rn.f32x2 %0, %1, %2, %0;" : "+l"(d) : "l"(a), "l"(b));
}
__device__ __forceinline__ float2 upk(u64 v) {
    float2 r; asm("mov.b64 {%0, %1}, %2;" : "=f"(r.x), "=f"(r.y) : "l"(v)); return r;
}

// ---------------------------------------------------------------------------
// Static device scratch (no cudaMalloc anywhere)
// ---------------------------------------------------------------------------
__device__ float g_x0[(size_t)TT * BB * 512];        // activation ping  (268 MB)
__device__ float g_x1[(size_t)TT * BB * 512];        // activation pong  (268 MB)
__device__ float g_xg[(size_t)2 * TT * BB * GG];     // input gates, 2 dirs (1.07 GB)
__device__ float g_h [2 * 2 * BB * HH];              // [parity][dir][B][H]
__device__ float g_c [2 * BB * HH];                  // [dir][B][H]
__device__ float g_dh[2 * 3 * BB * HH];              // [parity][layer][B][H]
__device__ float g_dc[3 * BB * HH];                  // [layer][B][H]
__device__ float g_inp[(size_t)BB * 512];            // decoder layer-0 input

// Software grid barrier state. g_gen is monotonically increasing across the
// whole process lifetime (wraps mod 2^32, compared by equality only), g_bar
// always returns to 0 — deterministic and graph-replay-safe with no resets.
__device__ unsigned int g_bar = 0u;
__device__ unsigned int g_gen = 0u;

__device__ __forceinline__ void grid_barrier(unsigned int nb) {
    __threadfence();              // every thread publishes its stores
    __syncthreads();
    if (threadIdx.x == 0) {
        unsigned int g = *((volatile unsigned int*)&g_gen);
        if (atomicAdd(&g_bar, 1u) == nb - 1u) {
            g_bar = 0u;           // all nb arrivals are in; safe plain store
            __threadfence();      // order bar reset before generation bump
            *((volatile unsigned int*)&g_gen) = g + 1u;
        } else {
            while (*((volatile unsigned int*)&g_gen) == g) { }
        }
        __threadfence();
    }
    __syncthreads();
}

__device__ __forceinline__ float sigf(float x) { return 1.f / (1.f + expf(-x)); }

// ---------------------------------------------------------------------------
// Zero helper
// ---------------------------------------------------------------------------
__global__ void zero_f32(float* p, int n) {
    int i = blockIdx.x * 256 + threadIdx.x;
    if (i < n) p[i] = 0.f;
}

// ---------------------------------------------------------------------------
// Embedding: x0[t][b][0:256] = emb[text[b][t]]
// ---------------------------------------------------------------------------
__global__ __launch_bounds__(256) void embed_kernel(
    const int* __restrict__ text,    // [B][T]
    const float* __restrict__ emb,   // [256][H]
    float* __restrict__ x0)          // [T][B][512]
{
    int r = blockIdx.x * 4 + (threadIdx.x >> 6);  // row = t*B + b
    int k = (threadIdx.x & 63) * 4;
    int t = r >> 8;
    int b = r & 255;
    int tok = text[b * TT + t];
    float4 v = *(const float4*)(emb + (size_t)tok * HH + k);
    *(float4*)(x0 + (size_t)r * 512 + k) = v;
}

// ---------------------------------------------------------------------------
// Input-gate GEMM: C[dir][m][n] = sum_k A[m][k] * W[dir][n][k] + bias[dir][n]
// 128x128x16 tile, 256 threads, 8x8 microtile (packed f32x2 along n).
// Double-buffered smem, 1 barrier per slab, LDG overlapped with compute.
// grid = (M/128, G/128, 2)
// ---------------------------------------------------------------------------
__global__ __launch_bounds__(256) void gemm_xg_kernel(
    const float* __restrict__ A,
    const float* __restrict__ Wb,     // [2][G][K]
    const float* __restrict__ bias,   // [2][G]
    float* __restrict__ C,            // [2][M][G]
    int K)
{
    const size_t M = (size_t)TT * BB;
    const int dir = blockIdx.z;
    const float* W  = Wb   + (size_t)dir * GG * K;
    const float* bd = bias + (size_t)dir * GG;
    float* Cd       = C    + (size_t)dir * M * GG;

    __shared__ alignas(16) float As[2][16][128];
    __shared__ alignas(16) float Bs[2][16][128];

    const int tid  = threadIdx.x;
    const int m0   = blockIdx.x * 128;
    const int n0   = blockIdx.y * 128;
    const int lrow = tid >> 1;
    const int lk   = (tid & 1) * 4;

    const float* Ap = A + (size_t)(m0 + lrow) * 512 + lk;
    const float* Wp = W + (size_t)(n0 + lrow) * K   + lk;

    const int ty = tid >> 4;
    const int tx = tid & 15;

    u64 acc2[8][4];
#pragma unroll
    for (int i = 0; i < 8; i++)
#pragma unroll
        for (int j = 0; j < 4; j++) acc2[i][j] = 0ull;

    {
        float4 av0 = *(const float4*)(Ap);
        float4 av1 = *(const float4*)(Ap + 8);
        float4 wv0 = *(const float4*)(Wp);
        float4 wv1 = *(const float4*)(Wp + 8);
        As[0][lk + 0][lrow] = av0.x; As[0][lk + 1][lrow] = av0.y;
        As[0][lk + 2][lrow] = av0.z; As[0][lk + 3][lrow] = av0.w;
        As[0][lk + 8][lrow] = av1.x; As[0][lk + 9][lrow] = av1.y;
        As[0][lk +10][lrow] = av1.z; As[0][lk +11][lrow] = av1.w;
        Bs[0][lk + 0][lrow] = wv0.x; Bs[0][lk + 1][lrow] = wv0.y;
        Bs[0][lk + 2][lrow] = wv0.z; Bs[0][lk + 3][lrow] = wv0.w;
        Bs[0][lk + 8][lrow] = wv1.x; Bs[0][lk + 9][lrow] = wv1.y;
        Bs[0][lk +10][lrow] = wv1.z; Bs[0][lk +11][lrow] = wv1.w;
    }
    __syncthreads();

    const int nslab = K >> 4;
    for (int i = 0; i < nslab; i++) {
        const int cur = i & 1;
        const bool more = (i + 1 < nslab);

        float4 av0, av1, wv0, wv1;
        if (more) {
            int k0 = (i + 1) << 4;
            av0 = *(const float4*)(Ap + k0);
            av1 = *(const float4*)(Ap + k0 + 8);
            wv0 = *(const float4*)(Wp + k0);
            wv1 = *(const float4*)(Wp + k0 + 8);
        }

#pragma unroll
        for (int kk = 0; kk < 16; kk++) {
            float a[8];
            *(float4*)&a[0] = *(const float4*)&As[cur][kk][ty * 8];
            *(float4*)&a[4] = *(const float4*)&As[cur][kk][ty * 8 + 4];
            ulonglong2 bp0 = *(const ulonglong2*)&Bs[cur][kk][tx * 8];
            ulonglong2 bp1 = *(const ulonglong2*)&Bs[cur][kk][tx * 8 + 4];
#pragma unroll
            for (int ii = 0; ii < 8; ii++) {
                u64 aa = pk2(a[ii], a[ii]);
                fma2(acc2[ii][0], aa, bp0.x);
                fma2(acc2[ii][1], aa, bp0.y);
                fma2(acc2[ii][2], aa, bp1.x);
                fma2(acc2[ii][3], aa, bp1.y);
            }
        }

        if (more) {
            const int nxt = cur ^ 1;
            As[nxt][lk + 0][lrow] = av0.x; As[nxt][lk + 1][lrow] = av0.y;
            As[nxt][lk + 2][lrow] = av0.z; As[nxt][lk + 3][lrow] = av0.w;
            As[nxt][lk + 8][lrow] = av1.x; As[nxt][lk + 9][lrow] = av1.y;
            As[nxt][lk +10][lrow] = av1.z; As[nxt][lk +11][lrow] = av1.w;
            Bs[nxt][lk + 0][lrow] = wv0.x; Bs[nxt][lk + 1][lrow] = wv0.y;
            Bs[nxt][lk + 2][lrow] = wv0.z; Bs[nxt][lk + 3][lrow] = wv0.w;
            Bs[nxt][lk + 8][lrow] = wv1.x; Bs[nxt][lk + 9][lrow] = wv1.y;
            Bs[nxt][lk +10][lrow] = wv1.z; Bs[nxt][lk +11][lrow] = wv1.w;
            __syncthreads();
        }
    }

    float bv[8];
#pragma unroll
    for (int j = 0; j < 8; j++) bv[j] = bd[n0 + tx * 8 + j];
#pragma unroll
    for (int i = 0; i < 8; i++) {
        size_t m = (size_t)(m0 + ty * 8 + i);
        float* cp = Cd + m * GG + n0 + tx * 8;
        float2 p0 = upk(acc2[i][0]);
        float2 p1 = upk(acc2[i][1]);
        float2 p2 = upk(acc2[i][2]);
        float2 p3 = upk(acc2[i][3]);
        float4 o0, o1;
        o0.x = p0.x + bv[0]; o0.y = p0.y + bv[1];
        o0.z = p1.x + bv[2]; o0.w = p1.y + bv[3];
        o1.x = p2.x + bv[4]; o1.y = p2.y + bv[5];
        o1.z = p3.x + bv[6]; o1.w = p3.y + bv[7];
        *(float4*)cp       = o0;
        *(float4*)(cp + 4) = o1;
    }
}

// ---------------------------------------------------------------------------
// Persistent encoder layer: all 512 timesteps in ONE launch.
// grid = (8 j-tiles, 8 b-tiles, 2 dirs) = 128 blocks (co-resident on 148 SMs),
// software grid barrier between timesteps. Inner body = double-buffered
// pipeline (1 block barrier per k-chunk, LDG overlapped with compute).
// ---------------------------------------------------------------------------
__global__ __launch_bounds__(256) void enc_layer_kernel(
    const float* __restrict__ xg,     // [2][T][B][G]
    const float* __restrict__ whh,    // [2][G][H]
    float* __restrict__ h,            // [2(parity)][2(dir)][B][H]
    float* __restrict__ c,            // [2(dir)][B][H]
    float* __restrict__ xout)         // [T][B][512]
{
    const int dir = blockIdx.z;
    const int j0  = blockIdx.x * 32;
    const int b0  = blockIdx.y * 32;
    const int tid = threadIdx.x;
    const unsigned int nb = gridDim.x * gridDim.y * gridDim.z;   // 128

    const float* W = whh + (size_t)dir * GG * HH;

    __shared__ alignas(16) float Ws[2][32][129];   // [buf][k][gate*32 + j]
    __shared__ alignas(16) float Hs[2][32][36];    // [buf][k][b] (row 144B)

    const int jl = tid & 31;
    const int bq = tid >> 5;        // 0..7 (warp-uniform)
    const int jr = tid >> 3;        // 0..31
    const int kq = tid & 7;         // 0..7

#pragma unroll 1
    for (int s = 0; s < TT; s++) {
        const int t = dir ? (TT - 1 - s) : s;
        const float* hi = h + (size_t)(s & 1) * 2 * BB * HH + (size_t)dir * BB * HH;
        float*       ho = h + (size_t)((s + 1) & 1) * 2 * BB * HH + (size_t)dir * BB * HH;

        u64 acc2[4][2];
#pragma unroll
        for (int g = 0; g < 4; g++) { acc2[g][0] = 0ull; acc2[g][1] = 0ull; }

        // prologue: chunk 0 -> buffer 0
        {
            float4 hv = *(const float4*)(hi + (size_t)(b0 + jr) * HH + kq * 4);
            Hs[0][kq * 4 + 0][jr] = hv.x; Hs[0][kq * 4 + 1][jr] = hv.y;
            Hs[0][kq * 4 + 2][jr] = hv.z; Hs[0][kq * 4 + 3][jr] = hv.w;
#pragma unroll
            for (int gt = 0; gt < 4; gt++) {
                int grow = gt * HH + j0 + jr;
                float4 v = *(const float4*)(W + (size_t)grow * HH + kq * 4);
                Ws[0][kq * 4 + 0][gt * 32 + jr] = v.x; Ws[0][kq * 4 + 1][gt * 32 + jr] = v.y;
                Ws[0][kq * 4 + 2][gt * 32 + jr] = v.z; Ws[0][kq * 4 + 3][gt * 32 + jr] = v.w;
            }
        }
        __syncthreads();

        const int nchunk = HH / 32;      // 8
#pragma unroll 1
        for (int i = 0; i < nchunk; i++) {
            const int cur = i & 1;
            const bool more = (i + 1 < nchunk);

            float4 hv, wv0, wv1, wv2, wv3;
            if (more) {
                int kc = (i + 1) * 32;
                hv  = *(const float4*)(hi + (size_t)(b0 + jr) * HH + kc + kq * 4);
                wv0 = *(const float4*)(W + (size_t)(0 * HH + j0 + jr) * HH + kc + kq * 4);
                wv1 = *(const float4*)(W + (size_t)(1 * HH + j0 + jr) * HH + kc + kq * 4);
                wv2 = *(const float4*)(W + (size_t)(2 * HH + j0 + jr) * HH + kc + kq * 4);
                wv3 = *(const float4*)(W + (size_t)(3 * HH + j0 + jr) * HH + kc + kq * 4);
            }

#pragma unroll
            for (int kk = 0; kk < 32; kk++) {
                ulonglong2 hp = *(const ulonglong2*)&Hs[cur][kk][bq * 4];
                u64 w0 = pk2(Ws[cur][kk][jl],      Ws[cur][kk][jl]);
                u64 w1 = pk2(Ws[cur][kk][32 + jl], Ws[cur][kk][32 + jl]);
                u64 w2 = pk2(Ws[cur][kk][64 + jl], Ws[cur][kk][64 + jl]);
                u64 w3 = pk2(Ws[cur][kk][96 + jl], Ws[cur][kk][96 + jl]);
                fma2(acc2[0][0], w0, hp.x); fma2(acc2[0][1], w0, hp.y);
                fma2(acc2[1][0], w1, hp.x); fma2(acc2[1][1], w1, hp.y);
                fma2(acc2[2][0], w2, hp.x); fma2(acc2[2][1], w2, hp.y);
                fma2(acc2[3][0], w3, hp.x); fma2(acc2[3][1], w3, hp.y);
            }

            if (more) {
                const int nxt = cur ^ 1;
                Hs[nxt][kq * 4 + 0][jr] = hv.x; Hs[nxt][kq * 4 + 1][jr] = hv.y;
                Hs[nxt][kq * 4 + 2][jr] = hv.z; Hs[nxt][kq * 4 + 3][jr] = hv.w;
                Ws[nxt][kq * 4 + 0][0 * 32 + jr] = wv0.x; Ws[nxt][kq * 4 + 1][0 * 32 + jr] = wv0.y;
                Ws[nxt][kq * 4 + 2][0 * 32 + jr] = wv0.z; Ws[nxt][kq * 4 + 3][0 * 32 + jr] = wv0.w;
                Ws[nxt][kq * 4 + 0][1 * 32 + jr] = wv1.x; Ws[nxt][kq * 4 + 1][1 * 32 + jr] = wv1.y;
                Ws[nxt][kq * 4 + 2][1 * 32 + jr] = wv1.z; Ws[nxt][kq * 4 + 3][1 * 32 + jr] = wv1.w;
                Ws[nxt][kq * 4 + 0][2 * 32 + jr] = wv2.x; Ws[nxt][kq * 4 + 1][2 * 32 + jr] = wv2.y;
                Ws[nxt][kq * 4 + 2][2 * 32 + jr] = wv2.z; Ws[nxt][kq * 4 + 3][2 * 32 + jr] = wv2.w;
                Ws[nxt][kq * 4 + 0][3 * 32 + jr] = wv3.x; Ws[nxt][kq * 4 + 1][3 * 32 + jr] = wv3.y;
                Ws[nxt][kq * 4 + 2][3 * 32 + jr] = wv3.z; Ws[nxt][kq * 4 + 3][3 * 32 + jr] = wv3.w;
                __syncthreads();
            }
        }

        float acc[4][4];
#pragma unroll
        for (int g = 0; g < 4; g++) {
            float2 pa  = upk(acc2[g][0]);
            float2 pbv = upk(acc2[g][1]);
            acc[g][0] = pa.x; acc[g][1] = pa.y; acc[g][2] = pbv.x; acc[g][3] = pbv.y;
        }

        const int j = j0 + jl;
        const float* xgp = xg + ((size_t)dir * TT + t) * (size_t)BB * GG;
#pragma unroll
        for (int bi = 0; bi < 4; bi++) {
            int b = b0 + bq * 4 + bi;
            size_t gbase = (size_t)b * GG + j;
            float gi = acc[0][bi] + xgp[gbase];
            float gf = acc[1][bi] + xgp[gbase + HH];
            float gg = acc[2][bi] + xgp[gbase + 2 * HH];
            float go = acc[3][bi] + xgp[gbase + 3 * HH];
            float si = sigf(gi), sf = sigf(gf), so = sigf(go);
            float tg = tanhf(gg);
            size_t cidx = (size_t)dir * BB * HH + (size_t)b * HH + j;
            float cn = sf * c[cidx] + si * tg;
            c[cidx] = cn;
            float hn = so * tanhf(cn);
            ho[(size_t)b * HH + j] = hn;
            xout[((size_t)t * BB + b) * 512 + dir * HH + j] = hn;
        }

        grid_barrier(nb);   // h_w visible to all blocks before next step
    }
}

// ---------------------------------------------------------------------------
// Decoder LSTM cell body (called from the persistent decoder kernel).
// Per thread: 4 gates x 2 batch (batch pair packed as f32x2).
// ---------------------------------------------------------------------------
__device__ __forceinline__ void dec_cell_body(
    const float* __restrict__ xin, int Kx,
    const float* __restrict__ wih,
    const float* __restrict__ whh,
    const float* __restrict__ bias,
    const float* __restrict__ h_in,
    float* __restrict__ h_out,
    float* __restrict__ c,
    int j0, int b0, int tid,
    float (*Ws)[129], float (*Xs)[18])
{
    const int jl  = tid & 31;
    const int bq  = tid >> 5;
    const int jr  = tid >> 3;
    const int kq  = tid & 7;
    const int xb  = tid >> 4;
    const int xk2 = (tid & 15) * 2;

    u64 acc2[4];
#pragma unroll
    for (int g = 0; g < 4; g++) acc2[g] = 0ull;

    const float* Wp = wih;
    const float* Xp = xin;
    int Klen = Kx;

#pragma unroll 1
    for (int phase = 0; phase < 2; phase++) {
#pragma unroll 1
        for (int kc = 0; kc < Klen; kc += 32) {
            __syncthreads();
            {
                float2 v = *(const float2*)(Xp + (size_t)(b0 + xb) * Klen + kc + xk2);
                Xs[xk2 + 0][xb] = v.x;
                Xs[xk2 + 1][xb] = v.y;
            }
#pragma unroll
            for (int gt = 0; gt < 4; gt++) {
                int grow = gt * HH + j0 + jr;
                float4 v = *(const float4*)(Wp + (size_t)grow * Klen + kc + kq * 4);
                Ws[kq * 4 + 0][gt * 32 + jr] = v.x; Ws[kq * 4 + 1][gt * 32 + jr] = v.y;
                Ws[kq * 4 + 2][gt * 32 + jr] = v.z; Ws[kq * 4 + 3][gt * 32 + jr] = v.w;
            }
            __syncthreads();
#pragma unroll
            for (int kk = 0; kk < 32; kk++) {
                u64 xp = *(const u64*)&Xs[kk][bq * 2];
                u64 w0 = pk2(Ws[kk][jl],      Ws[kk][jl]);
                u64 w1 = pk2(Ws[kk][32 + jl], Ws[kk][32 + jl]);
                u64 w2 = pk2(Ws[kk][64 + jl], Ws[kk][64 + jl]);
                u64 w3 = pk2(Ws[kk][96 + jl], Ws[kk][96 + jl]);
                fma2(acc2[0], w0, xp);
                fma2(acc2[1], w1, xp);
                fma2(acc2[2], w2, xp);
                fma2(acc2[3], w3, xp);
            }
        }
        Wp = whh; Xp = h_in; Klen = HH;
    }

    float acc[4][2];
#pragma unroll
    for (int g = 0; g < 4; g++) {
        float2 p = upk(acc2[g]);
        acc[g][0] = p.x; acc[g][1] = p.y;
    }

    const int j = j0 + jl;
#pragma unroll
    for (int bi = 0; bi < 2; bi++) {
        int b = b0 + bq * 2 + bi;
        float gi = acc[0][bi] + bias[j];
        float gf = acc[1][bi] + bias[HH + j];
        float gg = acc[2][bi] + bias[2 * HH + j];
        float go = acc[3][bi] + bias[3 * HH + j];
        float si = sigf(gi), sf = sigf(gf), so = sigf(go);
        float tg = tanhf(gg);
        size_t cidx = (size_t)b * HH + j;
        float cn = sf * c[cidx] + si * tg;
        c[cidx] = cn;
        h_out[cidx] = so * tanhf(cn);
    }
}

// ---------------------------------------------------------------------------
// Persistent decoder: all steps in ONE launch. 128 blocks, 256 threads.
// Per step: 3 cells (grid barrier after each) + proj/argmax/embed (2 batch
// rows per block) + end-of-step grid barrier.
// ---------------------------------------------------------------------------
__global__ __launch_bounds__(256) void dec_loop_kernel(
    int steps,
    const float* __restrict__ dwih0,   // [1024][512]
    const float* __restrict__ dwihR,   // [2][1024][256]
    const float* __restrict__ dwhh,    // [3][1024][256]
    const float* __restrict__ db,      // [3][1024]
    const float* __restrict__ pw,      // [256][256]
    const float* __restrict__ pb,      // [256]
    const float* __restrict__ emb,     // [256][256]
    float* __restrict__ dh,            // [2][3][B][H]
    float* __restrict__ dc,            // [3][B][H]
    float* __restrict__ inp,           // [B][512]
    float* __restrict__ out)           // [B][steps][256]
{
    const int bid = blockIdx.x;        // 0..127
    const int tid = threadIdx.x;
    const int j0  = (bid & 7) * 32;
    const int b0  = (bid >> 3) * 16;
    const unsigned int nb = gridDim.x; // 128

    __shared__ alignas(16) float Ws[32][129];
    __shared__ alignas(16) float Xs[32][18];
    __shared__ alignas(16) float hsh[256];
    __shared__ float sval[256];
    __shared__ int   sidx[256];
    __shared__ int   amax;

#pragma unroll 1
    for (int s = 0; s < steps; s++) {
        const int pr = s & 1;
        float* h_r = dh + (size_t)pr       * 3 * BB * HH;
        float* h_w = dh + (size_t)(1 - pr) * 3 * BB * HH;

#pragma unroll 1
        for (int l = 0; l < 3; l++) {
            const float* wih = (l == 0) ? dwih0 : dwihR + (size_t)(l - 1) * GG * HH;
            const int    Kx  = (l == 0) ? 512 : HH;
            const float* xin = (l == 0) ? inp : h_w + (size_t)(l - 1) * BB * HH;
            dec_cell_body(xin, Kx, wih,
                          dwhh + (size_t)l * GG * HH, db + l * GG,
                          h_r + (size_t)l * BB * HH,
                          h_w + (size_t)l * BB * HH,
                          dc  + (size_t)l * BB * HH,
                          j0, b0, tid, Ws, Xs);
            grid_barrier(nb);
        }

        // proj + argmax (first-index ties) + embedding feedback, 2 rows/block
        const float* h3 = h_w + (size_t)2 * BB * HH;
        const int v = tid;
#pragma unroll 1
        for (int r = 0; r < 2; r++) {
            const int b = bid * 2 + r;
            __syncthreads();
            hsh[v] = h3[(size_t)b * HH + v];
            __syncthreads();

            u64 a2 = 0ull;
            const u64* hp = (const u64*)hsh;
            const u64* wp = (const u64*)(pw + (size_t)v * HH);
#pragma unroll 8
            for (int k2 = 0; k2 < HH / 2; k2++) fma2(a2, hp[k2], wp[k2]);
            float2 ps = upk(a2);
            float acc = pb[v] + ps.x + ps.y;

            out[((size_t)b * steps + s) * 256 + v] = acc;

            sval[v] = acc;
            sidx[v] = v;
            __syncthreads();
#pragma unroll
            for (int off = 128; off >= 1; off >>= 1) {
                if (v < off) {
                    if (sval[v + off] > sval[v]) {   // strict > keeps lower index
                        sval[v] = sval[v + off];
                        sidx[v] = sidx[v + off];
                    }
                }
                __syncthreads();
            }
            if (v == 0) amax = sidx[0];
            __syncthreads();

            inp[(size_t)b * 512 + v]       = emb[(size_t)amax * HH + v];
            inp[(size_t)b * 512 + 256 + v] = 0.f;
        }
        grid_barrier(nb);   // inp/h_w visible before next step's layer 0
    }
}

// ---------------------------------------------------------------------------
// Copy first-timestep slice (contiguous [B][512]) into decoder input buffer.
// ---------------------------------------------------------------------------
__global__ void copy512_kernel(float* __restrict__ dst, const float* __restrict__ src) {
    int i = blockIdx.x * 256 + threadIdx.x;
    dst[i] = src[i];
}

// ---------------------------------------------------------------------------
// Host driver — 17 graph nodes total (was ~1950; fixes the 4 MiB
// graph-upload retention that tripped the harness memory rule).
// ---------------------------------------------------------------------------
extern "C" void kernel_launch(void* const* d_in, const int* in_sizes, int n_in,
                              void* d_out, int out_size) {
    const int*   text  = (const int*)  d_in[0];
    // d_in[1] = max_nefs_len (steps derived from out_size instead)
    const float* emb   = (const float*)d_in[2];
    const float* ewih0 = (const float*)d_in[3];   // [2][1024][256]
    const float* ewhh0 = (const float*)d_in[4];   // [2][1024][256]
    const float* eb0   = (const float*)d_in[5];   // [2][1024]
    const float* ewihR = (const float*)d_in[6];   // [2][2][1024][512]
    const float* ewhhR = (const float*)d_in[7];   // [2][2][1024][256]
    const float* ebR   = (const float*)d_in[8];   // [2][2][1024]
    const float* dwih0 = (const float*)d_in[9];   // [1024][512]
    const float* dwihR = (const float*)d_in[10];  // [2][1024][256]
    const float* dwhh  = (const float*)d_in[11];  // [3][1024][256]
    const float* db    = (const float*)d_in[12];  // [3][1024]
    const float* pw    = (const float*)d_in[13];  // [256][256]
    const float* pb    = (const float*)d_in[14];  // [256]
    float* out = (float*)d_out;

    const int steps = out_size / (BB * 256);      // = 100

    float *x0, *x1, *xg, *h, *c, *dh, *dc, *inp;
    cudaGetSymbolAddress((void**)&x0,  g_x0);
    cudaGetSymbolAddress((void**)&x1,  g_x1);
    cudaGetSymbolAddress((void**)&xg,  g_xg);
    cudaGetSymbolAddress((void**)&h,   g_h);
    cudaGetSymbolAddress((void**)&c,   g_c);
    cudaGetSymbolAddress((void**)&dh,  g_dh);
    cudaGetSymbolAddress((void**)&dc,  g_dc);
    cudaGetSymbolAddress((void**)&inp, g_inp);

    // 1. Embedding
    embed_kernel<<<(TT * BB) / 4, 256>>>(text, emb, x0);

    // 2. Encoder: 3 bidirectional layers (persistent recurrence kernels)
    float* xin   = x0;
    float* xnext = x1;
    for (int l = 0; l < 3; l++) {
        const float* wih; const float* whh; const float* bb; int K;
        if (l == 0) { wih = ewih0; whh = ewhh0; bb = eb0; K = 256; }
        else {
            wih = ewihR + (size_t)(l - 1) * 2 * GG * 512;
            whh = ewhhR + (size_t)(l - 1) * 2 * GG * HH;
            bb  = ebR   + (size_t)(l - 1) * 2 * GG;
            K = 512;
        }
        gemm_xg_kernel<<<dim3((TT * BB) / 128, GG / 128, 2), 256>>>(xin, wih, bb, xg, K);
        zero_f32<<<(2 * BB * HH) / 256, 256>>>(h, 2 * BB * HH);   // parity 0
        zero_f32<<<(2 * BB * HH) / 256, 256>>>(c, 2 * BB * HH);
        enc_layer_kernel<<<dim3(8, 8, 2), 256>>>(xg, whh, h, c, xnext);
        float* tmp = xin; xin = xnext; xnext = tmp;
    }
    // xin now holds enc_out, time-major [T][B][512]

    // 3. Decoder init
    copy512_kernel<<<(BB * 512) / 256, 256>>>(inp, xin);   // enc_out[:, 0, :] (t=0 slice contiguous)
    zero_f32<<<(3 * BB * HH) / 256, 256>>>(dh, 3 * BB * HH);   // parity 0
    zero_f32<<<(3 * BB * HH) / 256, 256>>>(dc, 3 * BB * HH);

    // 4. Decoder (persistent loop kernel)
    dec_loop_kernel<<<128, 256>>>(steps, dwih0, dwihR, dwhh, db, pw, pb, emb,
                                  dh, dc, inp, out);
}

// round 13
// speedup vs baseline: 1.1347x; 1.1347x over previous
#include <cuda_runtime.h>
#include <cuda_bf16.h>
#include <math.h>

// Fixed problem shapes
#define BB 256   // batch
#define TT 512   // encoder sequence length
#define HH 256   // hidden size
#define GG 1024  // 4*H gate rows

typedef unsigned long long u64;

// ---------------------------------------------------------------------------
// f32x2 packed-math helpers (bitwise identical to scalar FFMA per lane)
// ---------------------------------------------------------------------------
__device__ __forceinline__ u64 pk2(float lo, float hi) {
    u64 r; asm("mov.b64 %0, {%1, %2};" : "=l"(r) : "f"(lo), "f"(hi)); return r;
}
__device__ __forceinline__ void fma2(u64& d, u64 a, u64 b) {
    asm("fma.rn.f32x2 %0, %1, %2, %0;" : "+l"(d) : "l"(a), "l"(b));
}
__device__ __forceinline__ float2 upk(u64 v) {
    float2 r; asm("mov.b64 {%0, %1}, %2;" : "=f"(r.x), "=f"(r.y) : "l"(v)); return r;
}

// ---------------------------------------------------------------------------
// Static device scratch (no cudaMalloc anywhere)
// ---------------------------------------------------------------------------
__device__ float g_x0[(size_t)TT * BB * 512];        // activation ping  (268 MB)
__device__ float g_x1[(size_t)TT * BB * 512];        // activation pong  (268 MB)
__device__ float g_xg[(size_t)2 * TT * BB * GG];     // input gates, 2 dirs (1.07 GB)
__device__ float g_h [2 * 2 * BB * HH];              // [parity][dir][B][H]
__device__ float g_c [2 * BB * HH];                  // [dir][B][H]
__device__ float g_dh[2 * 3 * BB * HH];              // [parity][layer][B][H]
__device__ float g_dc[3 * BB * HH];                  // [layer][B][H]
__device__ float g_inp[(size_t)BB * 512];            // decoder layer-0 input

// Software grid barrier. g_gen increases monotonically across the process
// lifetime (equality-compared), g_bar always returns to 0 — deterministic
// and graph-replay-safe with no reset nodes.
__device__ unsigned int g_bar = 0u;
__device__ unsigned int g_gen = 0u;

__device__ __forceinline__ void grid_barrier(unsigned int nb) {
    __threadfence();
    __syncthreads();
    if (threadIdx.x == 0) {
        unsigned int g = *((volatile unsigned int*)&g_gen);
        if (atomicAdd(&g_bar, 1u) == nb - 1u) {
            g_bar = 0u;
            __threadfence();
            *((volatile unsigned int*)&g_gen) = g + 1u;
        } else {
            while (*((volatile unsigned int*)&g_gen) == g) { }
        }
        __threadfence();
    }
    __syncthreads();
}

__device__ __forceinline__ float sigf(float x) { return 1.f / (1.f + expf(-x)); }

// ---------------------------------------------------------------------------
// Embedding: x0[t][b][0:256] = emb[text[b][t]]
// ---------------------------------------------------------------------------
__global__ __launch_bounds__(256) void embed_kernel(
    const int* __restrict__ text,    // [B][T]
    const float* __restrict__ emb,   // [256][H]
    float* __restrict__ x0)          // [T][B][512]
{
    int r = blockIdx.x * 4 + (threadIdx.x >> 6);  // row = t*B + b
    int k = (threadIdx.x & 63) * 4;
    int t = r >> 8;
    int b = r & 255;
    int tok = text[b * TT + t];
    float4 v = *(const float4*)(emb + (size_t)tok * HH + k);
    *(float4*)(x0 + (size_t)r * 512 + k) = v;
}

// ---------------------------------------------------------------------------
// Input-gate GEMM: C[dir][m][n] = sum_k A[m][k] * W[dir][n][k] + bias[dir][n]
// 128x128x16 tile, 256 threads, 8x8 microtile (packed f32x2 along n).
// Double-buffered smem, 1 barrier per slab, LDG overlapped with compute.
// grid = (M/128, G/128, 2)
// ---------------------------------------------------------------------------
__global__ __launch_bounds__(256) void gemm_xg_kernel(
    const float* __restrict__ A,
    const float* __restrict__ Wb,     // [2][G][K]
    const float* __restrict__ bias,   // [2][G]
    float* __restrict__ C,            // [2][M][G]
    int K)
{
    const size_t M = (size_t)TT * BB;
    const int dir = blockIdx.z;
    const float* W  = Wb   + (size_t)dir * GG * K;
    const float* bd = bias + (size_t)dir * GG;
    float* Cd       = C    + (size_t)dir * M * GG;

    __shared__ alignas(16) float As[2][16][128];
    __shared__ alignas(16) float Bs[2][16][128];

    const int tid  = threadIdx.x;
    const int m0   = blockIdx.x * 128;
    const int n0   = blockIdx.y * 128;
    const int lrow = tid >> 1;
    const int lk   = (tid & 1) * 4;

    const float* Ap = A + (size_t)(m0 + lrow) * 512 + lk;
    const float* Wp = W + (size_t)(n0 + lrow) * K   + lk;

    const int ty = tid >> 4;
    const int tx = tid & 15;

    u64 acc2[8][4];
#pragma unroll
    for (int i = 0; i < 8; i++)
#pragma unroll
        for (int j = 0; j < 4; j++) acc2[i][j] = 0ull;

    {
        float4 av0 = *(const float4*)(Ap);
        float4 av1 = *(const float4*)(Ap + 8);
        float4 wv0 = *(const float4*)(Wp);
        float4 wv1 = *(const float4*)(Wp + 8);
        As[0][lk + 0][lrow] = av0.x; As[0][lk + 1][lrow] = av0.y;
        As[0][lk + 2][lrow] = av0.z; As[0][lk + 3][lrow] = av0.w;
        As[0][lk + 8][lrow] = av1.x; As[0][lk + 9][lrow] = av1.y;
        As[0][lk +10][lrow] = av1.z; As[0][lk +11][lrow] = av1.w;
        Bs[0][lk + 0][lrow] = wv0.x; Bs[0][lk + 1][lrow] = wv0.y;
        Bs[0][lk + 2][lrow] = wv0.z; Bs[0][lk + 3][lrow] = wv0.w;
        Bs[0][lk + 8][lrow] = wv1.x; Bs[0][lk + 9][lrow] = wv1.y;
        Bs[0][lk +10][lrow] = wv1.z; Bs[0][lk +11][lrow] = wv1.w;
    }
    __syncthreads();

    const int nslab = K >> 4;
    for (int i = 0; i < nslab; i++) {
        const int cur = i & 1;
        const bool more = (i + 1 < nslab);

        float4 av0, av1, wv0, wv1;
        if (more) {
            int k0 = (i + 1) << 4;
            av0 = *(const float4*)(Ap + k0);
            av1 = *(const float4*)(Ap + k0 + 8);
            wv0 = *(const float4*)(Wp + k0);
            wv1 = *(const float4*)(Wp + k0 + 8);
        }

#pragma unroll
        for (int kk = 0; kk < 16; kk++) {
            float a[8];
            *(float4*)&a[0] = *(const float4*)&As[cur][kk][ty * 8];
            *(float4*)&a[4] = *(const float4*)&As[cur][kk][ty * 8 + 4];
            ulonglong2 bp0 = *(const ulonglong2*)&Bs[cur][kk][tx * 8];
            ulonglong2 bp1 = *(const ulonglong2*)&Bs[cur][kk][tx * 8 + 4];
#pragma unroll
            for (int ii = 0; ii < 8; ii++) {
                u64 aa = pk2(a[ii], a[ii]);
                fma2(acc2[ii][0], aa, bp0.x);
                fma2(acc2[ii][1], aa, bp0.y);
                fma2(acc2[ii][2], aa, bp1.x);
                fma2(acc2[ii][3], aa, bp1.y);
            }
        }

        if (more) {
            const int nxt = cur ^ 1;
            As[nxt][lk + 0][lrow] = av0.x; As[nxt][lk + 1][lrow] = av0.y;
            As[nxt][lk + 2][lrow] = av0.z; As[nxt][lk + 3][lrow] = av0.w;
            As[nxt][lk + 8][lrow] = av1.x; As[nxt][lk + 9][lrow] = av1.y;
            As[nxt][lk +10][lrow] = av1.z; As[nxt][lk +11][lrow] = av1.w;
            Bs[nxt][lk + 0][lrow] = wv0.x; Bs[nxt][lk + 1][lrow] = wv0.y;
            Bs[nxt][lk + 2][lrow] = wv0.z; Bs[nxt][lk + 3][lrow] = wv0.w;
            Bs[nxt][lk + 8][lrow] = wv1.x; Bs[nxt][lk + 9][lrow] = wv1.y;
            Bs[nxt][lk +10][lrow] = wv1.z; Bs[nxt][lk +11][lrow] = wv1.w;
            __syncthreads();
        }
    }

    float bv[8];
#pragma unroll
    for (int j = 0; j < 8; j++) bv[j] = bd[n0 + tx * 8 + j];
#pragma unroll
    for (int i = 0; i < 8; i++) {
        size_t m = (size_t)(m0 + ty * 8 + i);
        float* cp = Cd + m * GG + n0 + tx * 8;
        float2 p0 = upk(acc2[i][0]);
        float2 p1 = upk(acc2[i][1]);
        float2 p2 = upk(acc2[i][2]);
        float2 p3 = upk(acc2[i][3]);
        float4 o0, o1;
        o0.x = p0.x + bv[0]; o0.y = p0.y + bv[1];
        o0.z = p1.x + bv[2]; o0.w = p1.y + bv[3];
        o1.x = p2.x + bv[4]; o1.y = p2.y + bv[5];
        o1.z = p3.x + bv[6]; o1.w = p3.y + bv[7];
        *(float4*)cp       = o0;
        *(float4*)(cp + 4) = o1;
    }
}

// ---------------------------------------------------------------------------
// Persistent encoder layer: zero-init + all 512 timesteps in ONE launch.
// grid = (8 j-tiles, 8 b-tiles, 2 dirs) = 128 blocks, grid barrier per step.
// xg values for the step are prefetched BEFORE the compute chunks so their
// DRAM latency hides under ~8.7k cycles of FMA2 work.
// ---------------------------------------------------------------------------
__global__ __launch_bounds__(256) void enc_layer_kernel(
    const float* __restrict__ xg,     // [2][T][B][G]
    const float* __restrict__ whh,    // [2][G][H]
    float* __restrict__ h,            // [2(parity)][2(dir)][B][H]
    float* __restrict__ c,            // [2(dir)][B][H]
    float* __restrict__ xout)         // [T][B][512]
{
    const int dir = blockIdx.z;
    const int j0  = blockIdx.x * 32;
    const int b0  = blockIdx.y * 32;
    const int tid = threadIdx.x;
    const unsigned int nb = gridDim.x * gridDim.y * gridDim.z;   // 128
    const int gtid = (((blockIdx.z * gridDim.y + blockIdx.y) * gridDim.x)
                      + blockIdx.x) * 256 + tid;                 // 0..32767

    // ---- fused init: zero h(parity 0) and c, then sync the grid ----
    {
        float4 z = make_float4(0.f, 0.f, 0.f, 0.f);
        *(float4*)(h + (size_t)gtid * 4) = z;    // 32768*4 = 131072 = 2*BB*HH
        *(float4*)(c + (size_t)gtid * 4) = z;
    }
    grid_barrier(nb);

    const float* W = whh + (size_t)dir * GG * HH;

    __shared__ alignas(16) float Ws[2][32][129];   // [buf][k][gate*32 + j]
    __shared__ alignas(16) float Hs[2][32][36];    // [buf][k][b] (row 144B)

    const int jl = tid & 31;
    const int bq = tid >> 5;        // 0..7 (warp-uniform)
    const int jr = tid >> 3;        // 0..31
    const int kq = tid & 7;         // 0..7
    const int j  = j0 + jl;

#pragma unroll 1
    for (int s = 0; s < TT; s++) {
        const int t = dir ? (TT - 1 - s) : s;
        const float* hi = h + (size_t)(s & 1) * 2 * BB * HH + (size_t)dir * BB * HH;
        float*       ho = h + (size_t)((s + 1) & 1) * 2 * BB * HH + (size_t)dir * BB * HH;

        // ---- prefetch this step's xg values (consumed in the epilogue) ----
        const float* xgp = xg + ((size_t)dir * TT + t) * (size_t)BB * GG;
        float xgv[4][4];   // [gate][bi]
#pragma unroll
        for (int bi = 0; bi < 4; bi++) {
            size_t gbase = (size_t)(b0 + bq * 4 + bi) * GG + j;
#pragma unroll
            for (int g = 0; g < 4; g++) xgv[g][bi] = xgp[gbase + g * HH];
        }

        u64 acc2[4][2];
#pragma unroll
        for (int g = 0; g < 4; g++) { acc2[g][0] = 0ull; acc2[g][1] = 0ull; }

        // prologue: chunk 0 -> buffer 0
        {
            float4 hv = *(const float4*)(hi + (size_t)(b0 + jr) * HH + kq * 4);
            Hs[0][kq * 4 + 0][jr] = hv.x; Hs[0][kq * 4 + 1][jr] = hv.y;
            Hs[0][kq * 4 + 2][jr] = hv.z; Hs[0][kq * 4 + 3][jr] = hv.w;
#pragma unroll
            for (int gt = 0; gt < 4; gt++) {
                int grow = gt * HH + j0 + jr;
                float4 v = *(const float4*)(W + (size_t)grow * HH + kq * 4);
                Ws[0][kq * 4 + 0][gt * 32 + jr] = v.x; Ws[0][kq * 4 + 1][gt * 32 + jr] = v.y;
                Ws[0][kq * 4 + 2][gt * 32 + jr] = v.z; Ws[0][kq * 4 + 3][gt * 32 + jr] = v.w;
            }
        }
        __syncthreads();

        const int nchunk = HH / 32;      // 8
#pragma unroll 1
        for (int i = 0; i < nchunk; i++) {
            const int cur = i & 1;
            const bool more = (i + 1 < nchunk);

            float4 hv, wv0, wv1, wv2, wv3;
            if (more) {
                int kc = (i + 1) * 32;
                hv  = *(const float4*)(hi + (size_t)(b0 + jr) * HH + kc + kq * 4);
                wv0 = *(const float4*)(W + (size_t)(0 * HH + j0 + jr) * HH + kc + kq * 4);
                wv1 = *(const float4*)(W + (size_t)(1 * HH + j0 + jr) * HH + kc + kq * 4);
                wv2 = *(const float4*)(W + (size_t)(2 * HH + j0 + jr) * HH + kc + kq * 4);
                wv3 = *(const float4*)(W + (size_t)(3 * HH + j0 + jr) * HH + kc + kq * 4);
            }

#pragma unroll
            for (int kk = 0; kk < 32; kk++) {
                ulonglong2 hp = *(const ulonglong2*)&Hs[cur][kk][bq * 4];
                u64 w0 = pk2(Ws[cur][kk][jl],      Ws[cur][kk][jl]);
                u64 w1 = pk2(Ws[cur][kk][32 + jl], Ws[cur][kk][32 + jl]);
                u64 w2 = pk2(Ws[cur][kk][64 + jl], Ws[cur][kk][64 + jl]);
                u64 w3 = pk2(Ws[cur][kk][96 + jl], Ws[cur][kk][96 + jl]);
                fma2(acc2[0][0], w0, hp.x); fma2(acc2[0][1], w0, hp.y);
                fma2(acc2[1][0], w1, hp.x); fma2(acc2[1][1], w1, hp.y);
                fma2(acc2[2][0], w2, hp.x); fma2(acc2[2][1], w2, hp.y);
                fma2(acc2[3][0], w3, hp.x); fma2(acc2[3][1], w3, hp.y);
            }

            if (more) {
                const int nxt = cur ^ 1;
                Hs[nxt][kq * 4 + 0][jr] = hv.x; Hs[nxt][kq * 4 + 1][jr] = hv.y;
                Hs[nxt][kq * 4 + 2][jr] = hv.z; Hs[nxt][kq * 4 + 3][jr] = hv.w;
                Ws[nxt][kq * 4 + 0][0 * 32 + jr] = wv0.x; Ws[nxt][kq * 4 + 1][0 * 32 + jr] = wv0.y;
                Ws[nxt][kq * 4 + 2][0 * 32 + jr] = wv0.z; Ws[nxt][kq * 4 + 3][0 * 32 + jr] = wv0.w;
                Ws[nxt][kq * 4 + 0][1 * 32 + jr] = wv1.x; Ws[nxt][kq * 4 + 1][1 * 32 + jr] = wv1.y;
                Ws[nxt][kq * 4 + 2][1 * 32 + jr] = wv1.z; Ws[nxt][kq * 4 + 3][1 * 32 + jr] = wv1.w;
                Ws[nxt][kq * 4 + 0][2 * 32 + jr] = wv2.x; Ws[nxt][kq * 4 + 1][2 * 32 + jr] = wv2.y;
                Ws[nxt][kq * 4 + 2][2 * 32 + jr] = wv2.z; Ws[nxt][kq * 4 + 3][2 * 32 + jr] = wv2.w;
                Ws[nxt][kq * 4 + 0][3 * 32 + jr] = wv3.x; Ws[nxt][kq * 4 + 1][3 * 32 + jr] = wv3.y;
                Ws[nxt][kq * 4 + 2][3 * 32 + jr] = wv3.z; Ws[nxt][kq * 4 + 3][3 * 32 + jr] = wv3.w;
                __syncthreads();
            }
        }

        float acc[4][4];
#pragma unroll
        for (int g = 0; g < 4; g++) {
            float2 pa  = upk(acc2[g][0]);
            float2 pbv = upk(acc2[g][1]);
            acc[g][0] = pa.x; acc[g][1] = pa.y; acc[g][2] = pbv.x; acc[g][3] = pbv.y;
        }

#pragma unroll
        for (int bi = 0; bi < 4; bi++) {
            int b = b0 + bq * 4 + bi;
            float gi = acc[0][bi] + xgv[0][bi];
            float gf = acc[1][bi] + xgv[1][bi];
            float gg = acc[2][bi] + xgv[2][bi];
            float go = acc[3][bi] + xgv[3][bi];
            float si = sigf(gi), sf = sigf(gf), so = sigf(go);
            float tg = tanhf(gg);
            size_t cidx = (size_t)dir * BB * HH + (size_t)b * HH + j;
            float cn = sf * c[cidx] + si * tg;
            c[cidx] = cn;
            float hn = so * tanhf(cn);
            ho[(size_t)b * HH + j] = hn;
            xout[((size_t)t * BB + b) * 512 + dir * HH + j] = hn;
        }

        grid_barrier(nb);   // h_out visible to all blocks before next step
    }
}

// ---------------------------------------------------------------------------
// Decoder LSTM cell body (inlined into the persistent decoder kernel).
// Per thread: 4 gates x 2 batch (batch pair packed as f32x2).
// ---------------------------------------------------------------------------
__device__ __forceinline__ void dec_cell_body(
    const float* __restrict__ xin, int Kx,
    const float* __restrict__ wih,
    const float* __restrict__ whh,
    const float* __restrict__ bias,
    const float* __restrict__ h_in,
    float* __restrict__ h_out,
    float* __restrict__ c,
    int j0, int b0, int tid,
    float (*Ws)[129], float (*Xs)[18])
{
    const int jl  = tid & 31;
    const int bq  = tid >> 5;
    const int jr  = tid >> 3;
    const int kq  = tid & 7;
    const int xb  = tid >> 4;
    const int xk2 = (tid & 15) * 2;

    u64 acc2[4];
#pragma unroll
    for (int g = 0; g < 4; g++) acc2[g] = 0ull;

    const float* Wp = wih;
    const float* Xp = xin;
    int Klen = Kx;

#pragma unroll 1
    for (int phase = 0; phase < 2; phase++) {
#pragma unroll 1
        for (int kc = 0; kc < Klen; kc += 32) {
            __syncthreads();
            {
                float2 v = *(const float2*)(Xp + (size_t)(b0 + xb) * Klen + kc + xk2);
                Xs[xk2 + 0][xb] = v.x;
                Xs[xk2 + 1][xb] = v.y;
            }
#pragma unroll
            for (int gt = 0; gt < 4; gt++) {
                int grow = gt * HH + j0 + jr;
                float4 v = *(const float4*)(Wp + (size_t)grow * Klen + kc + kq * 4);
                Ws[kq * 4 + 0][gt * 32 + jr] = v.x; Ws[kq * 4 + 1][gt * 32 + jr] = v.y;
                Ws[kq * 4 + 2][gt * 32 + jr] = v.z; Ws[kq * 4 + 3][gt * 32 + jr] = v.w;
            }
            __syncthreads();
#pragma unroll
            for (int kk = 0; kk < 32; kk++) {
                u64 xp = *(const u64*)&Xs[kk][bq * 2];
                u64 w0 = pk2(Ws[kk][jl],      Ws[kk][jl]);
                u64 w1 = pk2(Ws[kk][32 + jl], Ws[kk][32 + jl]);
                u64 w2 = pk2(Ws[kk][64 + jl], Ws[kk][64 + jl]);
                u64 w3 = pk2(Ws[kk][96 + jl], Ws[kk][96 + jl]);
                fma2(acc2[0], w0, xp);
                fma2(acc2[1], w1, xp);
                fma2(acc2[2], w2, xp);
                fma2(acc2[3], w3, xp);
            }
        }
        Wp = whh; Xp = h_in; Klen = HH;
    }

    float acc[4][2];
#pragma unroll
    for (int g = 0; g < 4; g++) {
        float2 p = upk(acc2[g]);
        acc[g][0] = p.x; acc[g][1] = p.y;
    }

    const int j = j0 + jl;
#pragma unroll
    for (int bi = 0; bi < 2; bi++) {
        int b = b0 + bq * 2 + bi;
        float gi = acc[0][bi] + bias[j];
        float gf = acc[1][bi] + bias[HH + j];
        float gg = acc[2][bi] + bias[2 * HH + j];
        float go = acc[3][bi] + bias[3 * HH + j];
        float si = sigf(gi), sf = sigf(gf), so = sigf(go);
        float tg = tanhf(gg);
        size_t cidx = (size_t)b * HH + j;
        float cn = sf * c[cidx] + si * tg;
        c[cidx] = cn;
        h_out[cidx] = so * tanhf(cn);
    }
}

// ---------------------------------------------------------------------------
// Persistent decoder: init (inp copy + zeros) + all steps in ONE launch.
// 128 blocks, 256 threads. Per step: 3 cells (grid barrier after each) +
// proj/argmax/embed (2 batch rows per block) + end-of-step grid barrier.
// ---------------------------------------------------------------------------
__global__ __launch_bounds__(256) void dec_loop_kernel(
    int steps,
    const float* __restrict__ enc0,    // enc_out base (t=0 slice = first B*512)
    const float* __restrict__ dwih0,   // [1024][512]
    const float* __restrict__ dwihR,   // [2][1024][256]
    const float* __restrict__ dwhh,    // [3][1024][256]
    const float* __restrict__ db,      // [3][1024]
    const float* __restrict__ pw,      // [256][256]
    const float* __restrict__ pb,      // [256]
    const float* __restrict__ emb,     // [256][256]
    float* __restrict__ dh,            // [2][3][B][H]
    float* __restrict__ dc,            // [3][B][H]
    float* __restrict__ inp,           // [B][512]
    float* __restrict__ out)           // [B][steps][256]
{
    const int bid = blockIdx.x;        // 0..127
    const int tid = threadIdx.x;
    const int j0  = (bid & 7) * 32;
    const int b0  = (bid >> 3) * 16;
    const unsigned int nb = gridDim.x; // 128
    const int gtid = bid * 256 + tid;  // 0..32767

    // ---- fused init: inp = enc_out[:,0,:], zero dh(parity0) + dc ----
    {
        *(float4*)(inp + (size_t)gtid * 4) =
            *(const float4*)(enc0 + (size_t)gtid * 4);   // 32768*4 = B*512
        float4 z = make_float4(0.f, 0.f, 0.f, 0.f);
#pragma unroll
        for (int rep = 0; rep < 2; rep++) {              // 2*65536 = 3*BB*HH... 
            size_t off = (size_t)(rep * 32768 + gtid) * 3;
            dh[off] = 0.f; dh[off + 1] = 0.f; dh[off + 2] = 0.f;
            dc[off] = 0.f; dc[off + 1] = 0.f; dc[off + 2] = 0.f;
        }
        (void)z;
    }
    grid_barrier(nb);

    __shared__ alignas(16) float Ws[32][129];
    __shared__ alignas(16) float Xs[32][18];
    __shared__ alignas(16) float hsh[256];
    __shared__ float sval[256];
    __shared__ int   sidx[256];
    __shared__ int   amax;

#pragma unroll 1
    for (int s = 0; s < steps; s++) {
        const int pr = s & 1;
        float* h_r = dh + (size_t)pr       * 3 * BB * HH;
        float* h_w = dh + (size_t)(1 - pr) * 3 * BB * HH;

#pragma unroll 1
        for (int l = 0; l < 3; l++) {
            const float* wih = (l == 0) ? dwih0 : dwihR + (size_t)(l - 1) * GG * HH;
            const int    Kx  = (l == 0) ? 512 : HH;
            const float* xin = (l == 0) ? inp : h_w + (size_t)(l - 1) * BB * HH;
            dec_cell_body(xin, Kx, wih,
                          dwhh + (size_t)l * GG * HH, db + l * GG,
                          h_r + (size_t)l * BB * HH,
                          h_w + (size_t)l * BB * HH,
                          dc  + (size_t)l * BB * HH,
                          j0, b0, tid, Ws, Xs);
            grid_barrier(nb);
        }

        // proj + argmax (first-index ties) + embedding feedback, 2 rows/block
        const float* h3 = h_w + (size_t)2 * BB * HH;
        const int v = tid;
#pragma unroll 1
        for (int r = 0; r < 2; r++) {
            const int b = bid * 2 + r;
            __syncthreads();
            hsh[v] = h3[(size_t)b * HH + v];
            __syncthreads();

            u64 a2 = 0ull;
            const u64* hp = (const u64*)hsh;
            const u64* wp = (const u64*)(pw + (size_t)v * HH);
#pragma unroll 8
            for (int k2 = 0; k2 < HH / 2; k2++) fma2(a2, hp[k2], wp[k2]);
            float2 ps = upk(a2);
            float acc = pb[v] + ps.x + ps.y;

            out[((size_t)b * steps + s) * 256 + v] = acc;

            sval[v] = acc;
            sidx[v] = v;
            __syncthreads();
#pragma unroll
            for (int off = 128; off >= 1; off >>= 1) {
                if (v < off) {
                    if (sval[v + off] > sval[v]) {   // strict > keeps lower index
                        sval[v] = sval[v + off];
                        sidx[v] = sidx[v + off];
                    }
                }
                __syncthreads();
            }
            if (v == 0) amax = sidx[0];
            __syncthreads();

            inp[(size_t)b * 512 + v]       = emb[(size_t)amax * HH + v];
            inp[(size_t)b * 512 + 256 + v] = 0.f;
        }
        grid_barrier(nb);   // inp/h_w visible before next step's layer 0
    }
}

// ---------------------------------------------------------------------------
// Host driver — 8 graph nodes: embed, (gemm, enc)x3, dec.
// Launch index 5 = layer-2 gemm, 6 = layer-2 enc: ncu (-s 5 -c 1) now
// profiles a dominant kernel instead of a zero-fill.
// ---------------------------------------------------------------------------
extern "C" void kernel_launch(void* const* d_in, const int* in_sizes, int n_in,
                              void* d_out, int out_size) {
    const int*   text  = (const int*)  d_in[0];
    // d_in[1] = max_nefs_len (steps derived from out_size instead)
    const float* emb   = (const float*)d_in[2];
    const float* ewih0 = (const float*)d_in[3];   // [2][1024][256]
    const float* ewhh0 = (const float*)d_in[4];   // [2][1024][256]
    const float* eb0   = (const float*)d_in[5];   // [2][1024]
    const float* ewihR = (const float*)d_in[6];   // [2][2][1024][512]
    const float* ewhhR = (const float*)d_in[7];   // [2][2][1024][256]
    const float* ebR   = (const float*)d_in[8];   // [2][2][1024]
    const float* dwih0 = (const float*)d_in[9];   // [1024][512]
    const float* dwihR = (const float*)d_in[10];  // [2][1024][256]
    const float* dwhh  = (const float*)d_in[11];  // [3][1024][256]
    const float* db    = (const float*)d_in[12];  // [3][1024]
    const float* pw    = (const float*)d_in[13];  // [256][256]
    const float* pb    = (const float*)d_in[14];  // [256]
    float* out = (float*)d_out;

    const int steps = out_size / (BB * 256);      // = 100

    float *x0, *x1, *xg, *h, *c, *dh, *dc, *inp;
    cudaGetSymbolAddress((void**)&x0,  g_x0);
    cudaGetSymbolAddress((void**)&x1,  g_x1);
    cudaGetSymbolAddress((void**)&xg,  g_xg);
    cudaGetSymbolAddress((void**)&h,   g_h);
    cudaGetSymbolAddress((void**)&c,   g_c);
    cudaGetSymbolAddress((void**)&dh,  g_dh);
    cudaGetSymbolAddress((void**)&dc,  g_dc);
    cudaGetSymbolAddress((void**)&inp, g_inp);

    // 1. Embedding
    embed_kernel<<<(TT * BB) / 4, 256>>>(text, emb, x0);

    // 2. Encoder: 3 bidirectional layers (persistent, self-initializing)
    float* xin   = x0;
    float* xnext = x1;
    for (int l = 0; l < 3; l++) {
        const float* wih; const float* whh; const float* bb; int K;
        if (l == 0) { wih = ewih0; whh = ewhh0; bb = eb0; K = 256; }
        else {
            wih = ewihR + (size_t)(l - 1) * 2 * GG * 512;
            whh = ewhhR + (size_t)(l - 1) * 2 * GG * HH;
            bb  = ebR   + (size_t)(l - 1) * 2 * GG;
            K = 512;
        }
        gemm_xg_kernel<<<dim3((TT * BB) / 128, GG / 128, 2), 256>>>(xin, wih, bb, xg, K);
        enc_layer_kernel<<<dim3(8, 8, 2), 256>>>(xg, whh, h, c, xnext);
        float* tmp = xin; xin = xnext; xnext = tmp;
    }
    // xin now holds enc_out, time-major [T][B][512]

    // 3. Decoder (persistent, self-initializing)
    dec_loop_kernel<<<128, 256>>>(steps, xin, dwih0, dwihR, dwhh, db, pw, pb,
                                  emb, dh, dc, inp, out);
}

// round 15
// speedup vs baseline: 1.2093x; 1.0657x over previous
#include <cuda_runtime.h>
#include <cuda_bf16.h>
#include <math.h>

// Fixed problem shapes
#define BB 256   // batch
#define TT 512   // encoder sequence length
#define HH 256   // hidden size
#define GG 1024  // 4*H gate rows

// Encoder smem layout (dynamic, opt-in)
#define ENC_WS 132                       // row stride for Ws[256][132]
#define ENC_HS 36                        // row stride for Hs[256][36]
#define ENC_SMEM_BYTES ((256 * ENC_WS + 256 * ENC_HS) * 4)   // 172032 B

typedef unsigned long long u64;

// ---------------------------------------------------------------------------
// f32x2 packed-math helpers (bitwise identical to scalar FFMA per lane)
// ---------------------------------------------------------------------------
__device__ __forceinline__ u64 pk2(float lo, float hi) {
    u64 r; asm("mov.b64 %0, {%1, %2};" : "=l"(r) : "f"(lo), "f"(hi)); return r;
}
__device__ __forceinline__ void fma2(u64& d, u64 a, u64 b) {
    asm("fma.rn.f32x2 %0, %1, %2, %0;" : "+l"(d) : "l"(a), "l"(b));
}
__device__ __forceinline__ float2 upk(u64 v) {
    float2 r; asm("mov.b64 {%0, %1}, %2;" : "=f"(r.x), "=f"(r.y) : "l"(v)); return r;
}

// ---------------------------------------------------------------------------
// Static device scratch (no cudaMalloc anywhere)
// ---------------------------------------------------------------------------
__device__ float g_x0[(size_t)TT * BB * 512];        // activation ping  (268 MB)
__device__ float g_x1[(size_t)TT * BB * 512];        // activation pong  (268 MB)
__device__ float g_xg[(size_t)2 * TT * BB * GG];     // input gates, 2 dirs (1.07 GB)
__device__ float g_h [2 * 2 * BB * HH];              // [parity][dir][B][H]
__device__ float g_c [2 * BB * HH];                  // [dir][B][H]
__device__ float g_dh[2 * 3 * BB * HH];              // [parity][layer][B][H]
__device__ float g_dc[3 * BB * HH];                  // [layer][B][H]
__device__ float g_inp[(size_t)BB * 512];            // decoder layer-0 input

// Software grid barrier. g_gen increases monotonically across the process
// lifetime (equality-compared), g_bar always returns to 0 — deterministic
// and graph-replay-safe with no reset nodes.
__device__ unsigned int g_bar = 0u;
__device__ unsigned int g_gen = 0u;

__device__ __forceinline__ void grid_barrier(unsigned int nb) {
    __threadfence();
    __syncthreads();
    if (threadIdx.x == 0) {
        unsigned int g = *((volatile unsigned int*)&g_gen);
        if (atomicAdd(&g_bar, 1u) == nb - 1u) {
            g_bar = 0u;
            __threadfence();
            *((volatile unsigned int*)&g_gen) = g + 1u;
        } else {
            while (*((volatile unsigned int*)&g_gen) == g) { }
        }
        __threadfence();
    }
    __syncthreads();
}

__device__ __forceinline__ float sigf(float x) { return 1.f / (1.f + expf(-x)); }

// ---------------------------------------------------------------------------
// No-op kernel: shifts launch indices so ncu (-s 5 -c 1) captures enc_layer.
// ---------------------------------------------------------------------------
__global__ void noop_kernel() {}

// ---------------------------------------------------------------------------
// Embedding: x0[t][b][0:256] = emb[text[b][t]]
// ---------------------------------------------------------------------------
__global__ __launch_bounds__(256) void embed_kernel(
    const int* __restrict__ text,    // [B][T]
    const float* __restrict__ emb,   // [256][H]
    float* __restrict__ x0)          // [T][B][512]
{
    int r = blockIdx.x * 4 + (threadIdx.x >> 6);  // row = t*B + b
    int k = (threadIdx.x & 63) * 4;
    int t = r >> 8;
    int b = r & 255;
    int tok = text[b * TT + t];
    float4 v = *(const float4*)(emb + (size_t)tok * HH + k);
    *(float4*)(x0 + (size_t)r * 512 + k) = v;
}

// ---------------------------------------------------------------------------
// Input-gate GEMM: C[dir][m][n] = sum_k A[m][k] * W[dir][n][k] + bias[dir][n]
// 128x128x16 tile, 256 threads, 8x8 microtile (packed f32x2 along n).
// Double-buffered smem, 1 barrier per slab, LDG overlapped with compute.
// __launch_bounds__(256, 2): cap regs at 128 so 2 blocks/SM are resident
// (measured occ was 12.4% at 130 regs; issue only 35%).
// grid = (M/128, G/128, 2)
// ---------------------------------------------------------------------------
__global__ __launch_bounds__(256, 2) void gemm_xg_kernel(
    const float* __restrict__ A,
    const float* __restrict__ Wb,     // [2][G][K]
    const float* __restrict__ bias,   // [2][G]
    float* __restrict__ C,            // [2][M][G]
    int K)
{
    const size_t M = (size_t)TT * BB;
    const int dir = blockIdx.z;
    const float* W  = Wb   + (size_t)dir * GG * K;
    const float* bd = bias + (size_t)dir * GG;
    float* Cd       = C    + (size_t)dir * M * GG;

    __shared__ alignas(16) float As[2][16][128];
    __shared__ alignas(16) float Bs[2][16][128];

    const int tid  = threadIdx.x;
    const int m0   = blockIdx.x * 128;
    const int n0   = blockIdx.y * 128;
    const int lrow = tid >> 1;
    const int lk   = (tid & 1) * 4;

    const float* Ap = A + (size_t)(m0 + lrow) * 512 + lk;
    const float* Wp = W + (size_t)(n0 + lrow) * K   + lk;

    const int ty = tid >> 4;
    const int tx = tid & 15;

    u64 acc2[8][4];
#pragma unroll
    for (int i = 0; i < 8; i++)
#pragma unroll
        for (int j = 0; j < 4; j++) acc2[i][j] = 0ull;

    {
        float4 av0 = *(const float4*)(Ap);
        float4 av1 = *(const float4*)(Ap + 8);
        float4 wv0 = *(const float4*)(Wp);
        float4 wv1 = *(const float4*)(Wp + 8);
        As[0][lk + 0][lrow] = av0.x; As[0][lk + 1][lrow] = av0.y;
        As[0][lk + 2][lrow] = av0.z; As[0][lk + 3][lrow] = av0.w;
        As[0][lk + 8][lrow] = av1.x; As[0][lk + 9][lrow] = av1.y;
        As[0][lk +10][lrow] = av1.z; As[0][lk +11][lrow] = av1.w;
        Bs[0][lk + 0][lrow] = wv0.x; Bs[0][lk + 1][lrow] = wv0.y;
        Bs[0][lk + 2][lrow] = wv0.z; Bs[0][lk + 3][lrow] = wv0.w;
        Bs[0][lk + 8][lrow] = wv1.x; Bs[0][lk + 9][lrow] = wv1.y;
        Bs[0][lk +10][lrow] = wv1.z; Bs[0][lk +11][lrow] = wv1.w;
    }
    __syncthreads();

    const int nslab = K >> 4;
    for (int i = 0; i < nslab; i++) {
        const int cur = i & 1;
        const bool more = (i + 1 < nslab);

        float4 av0, av1, wv0, wv1;
        if (more) {
            int k0 = (i + 1) << 4;
            av0 = *(const float4*)(Ap + k0);
            av1 = *(const float4*)(Ap + k0 + 8);
            wv0 = *(const float4*)(Wp + k0);
            wv1 = *(const float4*)(Wp + k0 + 8);
        }

#pragma unroll
        for (int kk = 0; kk < 16; kk++) {
            float a[8];
            *(float4*)&a[0] = *(const float4*)&As[cur][kk][ty * 8];
            *(float4*)&a[4] = *(const float4*)&As[cur][kk][ty * 8 + 4];
            ulonglong2 bp0 = *(const ulonglong2*)&Bs[cur][kk][tx * 8];
            ulonglong2 bp1 = *(const ulonglong2*)&Bs[cur][kk][tx * 8 + 4];
#pragma unroll
            for (int ii = 0; ii < 8; ii++) {
                u64 aa = pk2(a[ii], a[ii]);
                fma2(acc2[ii][0], aa, bp0.x);
                fma2(acc2[ii][1], aa, bp0.y);
                fma2(acc2[ii][2], aa, bp1.x);
                fma2(acc2[ii][3], aa, bp1.y);
            }
        }

        if (more) {
            const int nxt = cur ^ 1;
            As[nxt][lk + 0][lrow] = av0.x; As[nxt][lk + 1][lrow] = av0.y;
            As[nxt][lk + 2][lrow] = av0.z; As[nxt][lk + 3][lrow] = av0.w;
            As[nxt][lk + 8][lrow] = av1.x; As[nxt][lk + 9][lrow] = av1.y;
            As[nxt][lk +10][lrow] = av1.z; As[nxt][lk +11][lrow] = av1.w;
            Bs[nxt][lk + 0][lrow] = wv0.x; Bs[nxt][lk + 1][lrow] = wv0.y;
            Bs[nxt][lk + 2][lrow] = wv0.z; Bs[nxt][lk + 3][lrow] = wv0.w;
            Bs[nxt][lk + 8][lrow] = wv1.x; Bs[nxt][lk + 9][lrow] = wv1.y;
            Bs[nxt][lk +10][lrow] = wv1.z; Bs[nxt][lk +11][lrow] = wv1.w;
            __syncthreads();
        }
    }

    float bv[8];
#pragma unroll
    for (int j = 0; j < 8; j++) bv[j] = bd[n0 + tx * 8 + j];
#pragma unroll
    for (int i = 0; i < 8; i++) {
        size_t m = (size_t)(m0 + ty * 8 + i);
        float* cp = Cd + m * GG + n0 + tx * 8;
        float2 p0 = upk(acc2[i][0]);
        float2 p1 = upk(acc2[i][1]);
        float2 p2 = upk(acc2[i][2]);
        float2 p3 = upk(acc2[i][3]);
        float4 o0, o1;
        o0.x = p0.x + bv[0]; o0.y = p0.y + bv[1];
        o0.z = p1.x + bv[2]; o0.w = p1.y + bv[3];
        o1.x = p2.x + bv[4]; o1.y = p2.y + bv[5];
        o1.z = p3.x + bv[6]; o1.w = p3.y + bv[7];
        *(float4*)cp       = o0;
        *(float4*)(cp + 4) = o1;
    }
}

// ---------------------------------------------------------------------------
// Persistent encoder layer, W-resident-in-smem version.
// grid = (8 j-tiles, 8 b-tiles, 2 dirs) = 128 blocks, 256 threads.
// Block's 128KB Whh slice is loaded into dynamic smem ONCE; per step:
// xg prefetch + one cooperative h-tile load + ONE __syncthreads + 256
// barrier-free k-iterations + epilogue + grid barrier.
// ---------------------------------------------------------------------------
__global__ __launch_bounds__(256) void enc_layer_kernel(
    const float* __restrict__ xg,     // [2][T][B][G]
    const float* __restrict__ whh,    // [2][G][H]
    float* __restrict__ h,            // [2(parity)][2(dir)][B][H]
    float* __restrict__ c,            // [2(dir)][B][H]
    float* __restrict__ xout)         // [T][B][512]
{
    const int dir = blockIdx.z;
    const int j0  = blockIdx.x * 32;
    const int b0  = blockIdx.y * 32;
    const int tid = threadIdx.x;
    const unsigned int nb = gridDim.x * gridDim.y * gridDim.z;   // 128
    const int gtid = (((blockIdx.z * gridDim.y + blockIdx.y) * gridDim.x)
                      + blockIdx.x) * 256 + tid;                 // 0..32767

    extern __shared__ float smem_dyn[];
    float (*Ws)[ENC_WS] = (float(*)[ENC_WS])smem_dyn;                 // [256][132]
    float (*Hs)[ENC_HS] = (float(*)[ENC_HS])(smem_dyn + 256 * ENC_WS);// [256][36]

    const float* W = whh + (size_t)dir * GG * HH;

    const int jl = tid & 31;
    const int bq = tid >> 5;        // 0..7 (warp-uniform)
    const int jr = tid >> 3;        // 0..31
    const int kq = tid & 7;         // 0..7
    const int j  = j0 + jl;

    // ---- fused init: zero h(parity 0) and c ----
    {
        float4 z = make_float4(0.f, 0.f, 0.f, 0.f);
        *(float4*)(h + (size_t)gtid * 4) = z;    // 32768*4 = 2*BB*HH
        *(float4*)(c + (size_t)gtid * 4) = z;
    }

    // ---- one-time W preload: Ws[k][gt*32 + jr] = W[(gt*HH+j0+jr)*HH + k] ----
#pragma unroll
    for (int gt = 0; gt < 4; gt++) {
        const float* wrow = W + (size_t)(gt * HH + j0 + jr) * HH;
#pragma unroll
        for (int kc = 0; kc < HH; kc += 32) {
            float4 v = *(const float4*)(wrow + kc + kq * 4);
            int k = kc + kq * 4;
            Ws[k + 0][gt * 32 + jr] = v.x;
            Ws[k + 1][gt * 32 + jr] = v.y;
            Ws[k + 2][gt * 32 + jr] = v.z;
            Ws[k + 3][gt * 32 + jr] = v.w;
        }
    }
    grid_barrier(nb);   // h/c zeros visible everywhere; also syncs W stores

#pragma unroll 1
    for (int s = 0; s < TT; s++) {
        const int t = dir ? (TT - 1 - s) : s;
        const float* hi = h + (size_t)(s & 1) * 2 * BB * HH + (size_t)dir * BB * HH;
        float*       ho = h + (size_t)((s + 1) & 1) * 2 * BB * HH + (size_t)dir * BB * HH;

        // ---- prefetch this step's xg values (consumed in the epilogue) ----
        const float* xgp = xg + ((size_t)dir * TT + t) * (size_t)BB * GG;
        float xgv[4][4];   // [gate][bi]
#pragma unroll
        for (int bi = 0; bi < 4; bi++) {
            size_t gbase = (size_t)(b0 + bq * 4 + bi) * GG + j;
#pragma unroll
            for (int g = 0; g < 4; g++) xgv[g][bi] = xgp[gbase + g * HH];
        }

        // ---- cooperative h tile load: Hs[k][b] ----
#pragma unroll
        for (int kc = 0; kc < HH; kc += 32) {
            float4 hv = *(const float4*)(hi + (size_t)(b0 + jr) * HH + kc + kq * 4);
            int k = kc + kq * 4;
            Hs[k + 0][jr] = hv.x; Hs[k + 1][jr] = hv.y;
            Hs[k + 2][jr] = hv.z; Hs[k + 3][jr] = hv.w;
        }
        __syncthreads();

        u64 acc2[4][2];
#pragma unroll
        for (int g = 0; g < 4; g++) { acc2[g][0] = 0ull; acc2[g][1] = 0ull; }

        // ---- barrier-free inner loop over all 256 k ----
#pragma unroll 8
        for (int kk = 0; kk < HH; kk++) {
            ulonglong2 hp = *(const ulonglong2*)&Hs[kk][bq * 4];
            u64 w0 = pk2(Ws[kk][jl],      Ws[kk][jl]);
            u64 w1 = pk2(Ws[kk][32 + jl], Ws[kk][32 + jl]);
            u64 w2 = pk2(Ws[kk][64 + jl], Ws[kk][64 + jl]);
            u64 w3 = pk2(Ws[kk][96 + jl], Ws[kk][96 + jl]);
            fma2(acc2[0][0], w0, hp.x); fma2(acc2[0][1], w0, hp.y);
            fma2(acc2[1][0], w1, hp.x); fma2(acc2[1][1], w1, hp.y);
            fma2(acc2[2][0], w2, hp.x); fma2(acc2[2][1], w2, hp.y);
            fma2(acc2[3][0], w3, hp.x); fma2(acc2[3][1], w3, hp.y);
        }

        float acc[4][4];
#pragma unroll
        for (int g = 0; g < 4; g++) {
            float2 pa  = upk(acc2[g][0]);
            float2 pbv = upk(acc2[g][1]);
            acc[g][0] = pa.x; acc[g][1] = pa.y; acc[g][2] = pbv.x; acc[g][3] = pbv.y;
        }

#pragma unroll
        for (int bi = 0; bi < 4; bi++) {
            int b = b0 + bq * 4 + bi;
            float gi = acc[0][bi] + xgv[0][bi];
            float gf = acc[1][bi] + xgv[1][bi];
            float gg = acc[2][bi] + xgv[2][bi];
            float go = acc[3][bi] + xgv[3][bi];
            float si = sigf(gi), sf = sigf(gf), so = sigf(go);
            float tg = tanhf(gg);
            size_t cidx = (size_t)dir * BB * HH + (size_t)b * HH + j;
            float cn = sf * c[cidx] + si * tg;
            c[cidx] = cn;
            float hn = so * tanhf(cn);
            ho[(size_t)b * HH + j] = hn;
            xout[((size_t)t * BB + b) * 512 + dir * HH + j] = hn;
        }

        grid_barrier(nb);   // h_out visible to all blocks before next step
    }
}

// ---------------------------------------------------------------------------
// Decoder LSTM cell body (inlined into the persistent decoder kernel).
// Per thread: 4 gates x 2 batch (batch pair packed as f32x2).
// ---------------------------------------------------------------------------
__device__ __forceinline__ void dec_cell_body(
    const float* __restrict__ xin, int Kx,
    const float* __restrict__ wih,
    const float* __restrict__ whh,
    const float* __restrict__ bias,
    const float* __restrict__ h_in,
    float* __restrict__ h_out,
    float* __restrict__ c,
    int j0, int b0, int tid,
    float (*Ws)[129], float (*Xs)[18])
{
    const int jl  = tid & 31;
    const int bq  = tid >> 5;
    const int jr  = tid >> 3;
    const int kq  = tid & 7;
    const int xb  = tid >> 4;
    const int xk2 = (tid & 15) * 2;

    u64 acc2[4];
#pragma unroll
    for (int g = 0; g < 4; g++) acc2[g] = 0ull;

    const float* Wp = wih;
    const float* Xp = xin;
    int Klen = Kx;

#pragma unroll 1
    for (int phase = 0; phase < 2; phase++) {
#pragma unroll 1
        for (int kc = 0; kc < Klen; kc += 32) {
            __syncthreads();
            {
                float2 v = *(const float2*)(Xp + (size_t)(b0 + xb) * Klen + kc + xk2);
                Xs[xk2 + 0][xb] = v.x;
                Xs[xk2 + 1][xb] = v.y;
            }
#pragma unroll
            for (int gt = 0; gt < 4; gt++) {
                int grow = gt * HH + j0 + jr;
                float4 v = *(const float4*)(Wp + (size_t)grow * Klen + kc + kq * 4);
                Ws[kq * 4 + 0][gt * 32 + jr] = v.x; Ws[kq * 4 + 1][gt * 32 + jr] = v.y;
                Ws[kq * 4 + 2][gt * 32 + jr] = v.z; Ws[kq * 4 + 3][gt * 32 + jr] = v.w;
            }
            __syncthreads();
#pragma unroll
            for (int kk = 0; kk < 32; kk++) {
                u64 xp = *(const u64*)&Xs[kk][bq * 2];
                u64 w0 = pk2(Ws[kk][jl],      Ws[kk][jl]);
                u64 w1 = pk2(Ws[kk][32 + jl], Ws[kk][32 + jl]);
                u64 w2 = pk2(Ws[kk][64 + jl], Ws[kk][64 + jl]);
                u64 w3 = pk2(Ws[kk][96 + jl], Ws[kk][96 + jl]);
                fma2(acc2[0], w0, xp);
                fma2(acc2[1], w1, xp);
                fma2(acc2[2], w2, xp);
                fma2(acc2[3], w3, xp);
            }
        }
        Wp = whh; Xp = h_in; Klen = HH;
    }

    float acc[4][2];
#pragma unroll
    for (int g = 0; g < 4; g++) {
        float2 p = upk(acc2[g]);
        acc[g][0] = p.x; acc[g][1] = p.y;
    }

    const int j = j0 + jl;
#pragma unroll
    for (int bi = 0; bi < 2; bi++) {
        int b = b0 + bq * 2 + bi;
        float gi = acc[0][bi] + bias[j];
        float gf = acc[1][bi] + bias[HH + j];
        float gg = acc[2][bi] + bias[2 * HH + j];
        float go = acc[3][bi] + bias[3 * HH + j];
        float si = sigf(gi), sf = sigf(gf), so = sigf(go);
        float tg = tanhf(gg);
        size_t cidx = (size_t)b * HH + j;
        float cn = sf * c[cidx] + si * tg;
        c[cidx] = cn;
        h_out[cidx] = so * tanhf(cn);
    }
}

// ---------------------------------------------------------------------------
// Persistent decoder: init (inp copy + zeros) + all steps in ONE launch.
// 128 blocks, 256 threads. Per step: 3 cells (grid barrier after each) +
// proj/argmax/embed (2 batch rows per block) + end-of-step grid barrier.
// ---------------------------------------------------------------------------
__global__ __launch_bounds__(256) void dec_loop_kernel(
    int steps,
    const float* __restrict__ enc0,    // enc_out base (t=0 slice = first B*512)
    const float* __restrict__ dwih0,   // [1024][512]
    const float* __restrict__ dwihR,   // [2][1024][256]
    const float* __restrict__ dwhh,    // [3][1024][256]
    const float* __restrict__ db,      // [3][1024]
    const float* __restrict__ pw,      // [256][256]
    const float* __restrict__ pb,      // [256]
    const float* __restrict__ emb,     // [256][256]
    float* __restrict__ dh,            // [2][3][B][H]
    float* __restrict__ dc,            // [3][B][H]
    float* __restrict__ inp,           // [B][512]
    float* __restrict__ out)           // [B][steps][256]
{
    const int bid = blockIdx.x;        // 0..127
    const int tid = threadIdx.x;
    const int j0  = (bid & 7) * 32;
    const int b0  = (bid >> 3) * 16;
    const unsigned int nb = gridDim.x; // 128
    const int gtid = bid * 256 + tid;  // 0..32767

    // ---- fused init: inp = enc_out[:,0,:], zero dh(parity0) + dc ----
    {
        *(float4*)(inp + (size_t)gtid * 4) =
            *(const float4*)(enc0 + (size_t)gtid * 4);   // 32768*4 = B*512
#pragma unroll
        for (int rep = 0; rep < 2; rep++) {              // covers 3*BB*HH each
            size_t off = (size_t)(rep * 32768 + gtid) * 3;
            dh[off] = 0.f; dh[off + 1] = 0.f; dh[off + 2] = 0.f;
            dc[off] = 0.f; dc[off + 1] = 0.f; dc[off + 2] = 0.f;
        }
    }
    grid_barrier(nb);

    __shared__ alignas(16) float Ws[32][129];
    __shared__ alignas(16) float Xs[32][18];
    __shared__ alignas(16) float hsh[256];
    __shared__ float sval[256];
    __shared__ int   sidx[256];
    __shared__ int   amax;

#pragma unroll 1
    for (int s = 0; s < steps; s++) {
        const int pr = s & 1;
        float* h_r = dh + (size_t)pr       * 3 * BB * HH;
        float* h_w = dh + (size_t)(1 - pr) * 3 * BB * HH;

#pragma unroll 1
        for (int l = 0; l < 3; l++) {
            const float* wih = (l == 0) ? dwih0 : dwihR + (size_t)(l - 1) * GG * HH;
            const int    Kx  = (l == 0) ? 512 : HH;
            const float* xin = (l == 0) ? inp : h_w + (size_t)(l - 1) * BB * HH;
            dec_cell_body(xin, Kx, wih,
                          dwhh + (size_t)l * GG * HH, db + l * GG,
                          h_r + (size_t)l * BB * HH,
                          h_w + (size_t)l * BB * HH,
                          dc  + (size_t)l * BB * HH,
                          j0, b0, tid, Ws, Xs);
            grid_barrier(nb);
        }

        // proj + argmax (first-index ties) + embedding feedback, 2 rows/block
        const float* h3 = h_w + (size_t)2 * BB * HH;
        const int v = tid;
#pragma unroll 1
        for (int r = 0; r < 2; r++) {
            const int b = bid * 2 + r;
            __syncthreads();
            hsh[v] = h3[(size_t)b * HH + v];
            __syncthreads();

            u64 a2 = 0ull;
            const u64* hp = (const u64*)hsh;
            const u64* wp = (const u64*)(pw + (size_t)v * HH);
#pragma unroll 8
            for (int k2 = 0; k2 < HH / 2; k2++) fma2(a2, hp[k2], wp[k2]);
            float2 ps = upk(a2);
            float acc = pb[v] + ps.x + ps.y;

            out[((size_t)b * steps + s) * 256 + v] = acc;

            sval[v] = acc;
            sidx[v] = v;
            __syncthreads();
#pragma unroll
            for (int off = 128; off >= 1; off >>= 1) {
                if (v < off) {
                    if (sval[v + off] > sval[v]) {   // strict > keeps lower index
                        sval[v] = sval[v + off];
                        sidx[v] = sidx[v + off];
                    }
                }
                __syncthreads();
            }
            if (v == 0) amax = sidx[0];
            __syncthreads();

            inp[(size_t)b * 512 + v]       = emb[(size_t)amax * HH + v];
            inp[(size_t)b * 512 + 256 + v] = 0.f;
        }
        grid_barrier(nb);   // inp/h_w visible before next step's layer 0
    }
}

// ---------------------------------------------------------------------------
// Host driver — 9 graph nodes: noop, embed, (gemm, enc)x3, dec.
// ncu -s 5 -c 1 lands on enc_layer_kernel (layer 1).
// ---------------------------------------------------------------------------
extern "C" void kernel_launch(void* const* d_in, const int* in_sizes, int n_in,
                              void* d_out, int out_size) {
    const int*   text  = (const int*)  d_in[0];
    // d_in[1] = max_nefs_len (steps derived from out_size instead)
    const float* emb   = (const float*)d_in[2];
    const float* ewih0 = (const float*)d_in[3];   // [2][1024][256]
    const float* ewhh0 = (const float*)d_in[4];   // [2][1024][256]
    const float* eb0   = (const float*)d_in[5];   // [2][1024]
    const float* ewihR = (const float*)d_in[6];   // [2][2][1024][512]
    const float* ewhhR = (const float*)d_in[7];   // [2][2][1024][256]
    const float* ebR   = (const float*)d_in[8];   // [2][2][1024]
    const float* dwih0 = (const float*)d_in[9];   // [1024][512]
    const float* dwihR = (const float*)d_in[10];  // [2][1024][256]
    const float* dwhh  = (const float*)d_in[11];  // [3][1024][256]
    const float* db    = (const float*)d_in[12];  // [3][1024]
    const float* pw    = (const float*)d_in[13];  // [256][256]
    const float* pb    = (const float*)d_in[14];  // [256]
    float* out = (float*)d_out;

    const int steps = out_size / (BB * 256);      // = 100

    float *x0, *x1, *xg, *h, *c, *dh, *dc, *inp;
    cudaGetSymbolAddress((void**)&x0,  g_x0);
    cudaGetSymbolAddress((void**)&x1,  g_x1);
    cudaGetSymbolAddress((void**)&xg,  g_xg);
    cudaGetSymbolAddress((void**)&h,   g_h);
    cudaGetSymbolAddress((void**)&c,   g_c);
    cudaGetSymbolAddress((void**)&dh,  g_dh);
    cudaGetSymbolAddress((void**)&dc,  g_dc);
    cudaGetSymbolAddress((void**)&inp, g_inp);

    // Enable 168KB dynamic smem for the encoder (idempotent; not a stream op)
    cudaFuncSetAttribute(enc_layer_kernel,
                         cudaFuncAttributeMaxDynamicSharedMemorySize,
                         ENC_SMEM_BYTES);

    // 0. Launch-index shim for ncu
    noop_kernel<<<1, 1>>>();

    // 1. Embedding
    embed_kernel<<<(TT * BB) / 4, 256>>>(text, emb, x0);

    // 2. Encoder: 3 bidirectional layers (persistent, self-initializing)
    float* xin   = x0;
    float* xnext = x1;
    for (int l = 0; l < 3; l++) {
        const float* wih; const float* whh; const float* bb; int K;
        if (l == 0) { wih = ewih0; whh = ewhh0; bb = eb0; K = 256; }
        else {
            wih = ewihR + (size_t)(l - 1) * 2 * GG * 512;
            whh = ewhhR + (size_t)(l - 1) * 2 * GG * HH;
            bb  = ebR   + (size_t)(l - 1) * 2 * GG;
            K = 512;
        }
        gemm_xg_kernel<<<dim3((TT * BB) / 128, GG / 128, 2), 256>>>(xin, wih, bb, xg, K);
        enc_layer_kernel<<<dim3(8, 8, 2), 256, ENC_SMEM_BYTES>>>(xg, whh, h, c, xnext);
        float* tmp = xin; xin = xnext; xnext = tmp;
    }
    // xin now holds enc_out, time-major [T][B][512]

    // 3. Decoder (persistent, self-initializing)
    dec_loop_kernel<<<128, 256>>>(steps, xin, dwih0, dwihR, dwhh, db, pw, pb,
                                  emb, dh, dc, inp, out);
}

// round 16
// speedup vs baseline: 1.2160x; 1.0055x over previous
#include <cuda_runtime.h>
#include <cuda_bf16.h>
#include <math.h>

// Fixed problem shapes
#define BB 256   // batch
#define TT 512   // encoder sequence length
#define HH 256   // hidden size
#define GG 1024  // 4*H gate rows

// Encoder smem layout (dynamic, opt-in)
#define ENC_WS 132                       // row stride for WsI[256][132]
#define ENC_HS 36                        // row stride for Hs[256][36]
#define ENC_SMEM_BYTES ((256 * ENC_WS + 256 * ENC_HS) * 4)   // 172032 B

typedef unsigned long long u64;

// ---------------------------------------------------------------------------
// f32x2 packed-math helpers (bitwise identical to scalar FFMA per lane)
// ---------------------------------------------------------------------------
__device__ __forceinline__ u64 pk2(float lo, float hi) {
    u64 r; asm("mov.b64 %0, {%1, %2};" : "=l"(r) : "f"(lo), "f"(hi)); return r;
}
__device__ __forceinline__ void fma2(u64& d, u64 a, u64 b) {
    asm("fma.rn.f32x2 %0, %1, %2, %0;" : "+l"(d) : "l"(a), "l"(b));
}
__device__ __forceinline__ float2 upk(u64 v) {
    float2 r; asm("mov.b64 {%0, %1}, %2;" : "=f"(r.x), "=f"(r.y) : "l"(v)); return r;
}

// ---------------------------------------------------------------------------
// Static device scratch (no cudaMalloc anywhere)
// ---------------------------------------------------------------------------
__device__ float g_x0[(size_t)TT * BB * 512];        // activation ping  (268 MB)
__device__ float g_x1[(size_t)TT * BB * 512];        // activation pong  (268 MB)
__device__ float g_xg[(size_t)2 * TT * BB * GG];     // input gates, 2 dirs (1.07 GB)
__device__ float g_h [2 * 2 * BB * HH];              // [parity][dir][B][H]
__device__ float g_dh[2 * 3 * BB * HH];              // [parity][layer][B][H]
__device__ float g_dc[3 * BB * HH];                  // [layer][B][H]
__device__ float g_inp[(size_t)BB * 512];            // decoder layer-0 input

// Global grid barrier (full grid): monotonically increasing generation,
// counter always returns to 0 — deterministic and graph-replay-safe.
__device__ unsigned int g_bar = 0u;
__device__ unsigned int g_gen = 0u;

// Per-direction barrier slots, padded to separate cache lines.
__device__ unsigned int g_bard[64];   // slot 0 -> [0], slot 1 -> [32]
__device__ unsigned int g_gend[64];

__device__ __forceinline__ void grid_barrier(unsigned int nb) {
    __threadfence();
    __syncthreads();
    if (threadIdx.x == 0) {
        unsigned int g = *((volatile unsigned int*)&g_gen);
        if (atomicAdd(&g_bar, 1u) == nb - 1u) {
            g_bar = 0u;
            __threadfence();
            *((volatile unsigned int*)&g_gen) = g + 1u;
        } else {
            while (*((volatile unsigned int*)&g_gen) == g) { }
        }
        __threadfence();
    }
    __syncthreads();
}

__device__ __forceinline__ void grid_barrier_slot(unsigned int nb, int idx) {
    __threadfence();
    __syncthreads();
    if (threadIdx.x == 0) {
        unsigned int g = *((volatile unsigned int*)&g_gend[idx]);
        if (atomicAdd(&g_bard[idx], 1u) == nb - 1u) {
            g_bard[idx] = 0u;
            __threadfence();
            *((volatile unsigned int*)&g_gend[idx]) = g + 1u;
        } else {
            while (*((volatile unsigned int*)&g_gend[idx]) == g) { }
        }
        __threadfence();
    }
    __syncthreads();
}

__device__ __forceinline__ float sigf(float x) { return 1.f / (1.f + expf(-x)); }

// ---------------------------------------------------------------------------
// No-op kernel: shifts launch indices so ncu (-s 5 -c 1) captures enc_layer.
// ---------------------------------------------------------------------------
__global__ void noop_kernel() {}

// ---------------------------------------------------------------------------
// Embedding: x0[t][b][0:256] = emb[text[b][t]]
// ---------------------------------------------------------------------------
__global__ __launch_bounds__(256) void embed_kernel(
    const int* __restrict__ text,    // [B][T]
    const float* __restrict__ emb,   // [256][H]
    float* __restrict__ x0)          // [T][B][512]
{
    int r = blockIdx.x * 4 + (threadIdx.x >> 6);  // row = t*B + b
    int k = (threadIdx.x & 63) * 4;
    int t = r >> 8;
    int b = r & 255;
    int tok = text[b * TT + t];
    float4 v = *(const float4*)(emb + (size_t)tok * HH + k);
    *(float4*)(x0 + (size_t)r * 512 + k) = v;
}

// ---------------------------------------------------------------------------
// Input-gate GEMM: C[dir][m][n] = sum_k A[m][k] * W[dir][n][k] + bias[dir][n]
// 128x128x16 tile, 256 threads, 8x8 microtile (packed f32x2 along n).
// Double-buffered smem, 1 barrier per slab, LDG overlapped with compute.
// __launch_bounds__(256, 2): 2 blocks/SM resident.
// grid = (M/128, G/128, 2)
// ---------------------------------------------------------------------------
__global__ __launch_bounds__(256, 2) void gemm_xg_kernel(
    const float* __restrict__ A,
    const float* __restrict__ Wb,     // [2][G][K]
    const float* __restrict__ bias,   // [2][G]
    float* __restrict__ C,            // [2][M][G]
    int K)
{
    const size_t M = (size_t)TT * BB;
    const int dir = blockIdx.z;
    const float* W  = Wb   + (size_t)dir * GG * K;
    const float* bd = bias + (size_t)dir * GG;
    float* Cd       = C    + (size_t)dir * M * GG;

    __shared__ alignas(16) float As[2][16][128];
    __shared__ alignas(16) float Bs[2][16][128];

    const int tid  = threadIdx.x;
    const int m0   = blockIdx.x * 128;
    const int n0   = blockIdx.y * 128;
    const int lrow = tid >> 1;
    const int lk   = (tid & 1) * 4;

    const float* Ap = A + (size_t)(m0 + lrow) * 512 + lk;
    const float* Wp = W + (size_t)(n0 + lrow) * K   + lk;

    const int ty = tid >> 4;
    const int tx = tid & 15;

    u64 acc2[8][4];
#pragma unroll
    for (int i = 0; i < 8; i++)
#pragma unroll
        for (int j = 0; j < 4; j++) acc2[i][j] = 0ull;

    {
        float4 av0 = *(const float4*)(Ap);
        float4 av1 = *(const float4*)(Ap + 8);
        float4 wv0 = *(const float4*)(Wp);
        float4 wv1 = *(const float4*)(Wp + 8);
        As[0][lk + 0][lrow] = av0.x; As[0][lk + 1][lrow] = av0.y;
        As[0][lk + 2][lrow] = av0.z; As[0][lk + 3][lrow] = av0.w;
        As[0][lk + 8][lrow] = av1.x; As[0][lk + 9][lrow] = av1.y;
        As[0][lk +10][lrow] = av1.z; As[0][lk +11][lrow] = av1.w;
        Bs[0][lk + 0][lrow] = wv0.x; Bs[0][lk + 1][lrow] = wv0.y;
        Bs[0][lk + 2][lrow] = wv0.z; Bs[0][lk + 3][lrow] = wv0.w;
        Bs[0][lk + 8][lrow] = wv1.x; Bs[0][lk + 9][lrow] = wv1.y;
        Bs[0][lk +10][lrow] = wv1.z; Bs[0][lk +11][lrow] = wv1.w;
    }
    __syncthreads();

    const int nslab = K >> 4;
    for (int i = 0; i < nslab; i++) {
        const int cur = i & 1;
        const bool more = (i + 1 < nslab);

        float4 av0, av1, wv0, wv1;
        if (more) {
            int k0 = (i + 1) << 4;
            av0 = *(const float4*)(Ap + k0);
            av1 = *(const float4*)(Ap + k0 + 8);
            wv0 = *(const float4*)(Wp + k0);
            wv1 = *(const float4*)(Wp + k0 + 8);
        }

#pragma unroll
        for (int kk = 0; kk < 16; kk++) {
            float a[8];
            *(float4*)&a[0] = *(const float4*)&As[cur][kk][ty * 8];
            *(float4*)&a[4] = *(const float4*)&As[cur][kk][ty * 8 + 4];
            ulonglong2 bp0 = *(const ulonglong2*)&Bs[cur][kk][tx * 8];
            ulonglong2 bp1 = *(const ulonglong2*)&Bs[cur][kk][tx * 8 + 4];
#pragma unroll
            for (int ii = 0; ii < 8; ii++) {
                u64 aa = pk2(a[ii], a[ii]);
                fma2(acc2[ii][0], aa, bp0.x);
                fma2(acc2[ii][1], aa, bp0.y);
                fma2(acc2[ii][2], aa, bp1.x);
                fma2(acc2[ii][3], aa, bp1.y);
            }
        }

        if (more) {
            const int nxt = cur ^ 1;
            As[nxt][lk + 0][lrow] = av0.x; As[nxt][lk + 1][lrow] = av0.y;
            As[nxt][lk + 2][lrow] = av0.z; As[nxt][lk + 3][lrow] = av0.w;
            As[nxt][lk + 8][lrow] = av1.x; As[nxt][lk + 9][lrow] = av1.y;
            As[nxt][lk +10][lrow] = av1.z; As[nxt][lk +11][lrow] = av1.w;
            Bs[nxt][lk + 0][lrow] = wv0.x; Bs[nxt][lk + 1][lrow] = wv0.y;
            Bs[nxt][lk + 2][lrow] = wv0.z; Bs[nxt][lk + 3][lrow] = wv0.w;
            Bs[nxt][lk + 8][lrow] = wv1.x; Bs[nxt][lk + 9][lrow] = wv1.y;
            Bs[nxt][lk +10][lrow] = wv1.z; Bs[nxt][lk +11][lrow] = wv1.w;
            __syncthreads();
        }
    }

    float bv[8];
#pragma unroll
    for (int j = 0; j < 8; j++) bv[j] = bd[n0 + tx * 8 + j];
#pragma unroll
    for (int i = 0; i < 8; i++) {
        size_t m = (size_t)(m0 + ty * 8 + i);
        float* cp = Cd + m * GG + n0 + tx * 8;
        float2 p0 = upk(acc2[i][0]);
        float2 p1 = upk(acc2[i][1]);
        float2 p2 = upk(acc2[i][2]);
        float2 p3 = upk(acc2[i][3]);
        float4 o0, o1;
        o0.x = p0.x + bv[0]; o0.y = p0.y + bv[1];
        o0.z = p1.x + bv[2]; o0.w = p1.y + bv[3];
        o1.x = p2.x + bv[4]; o1.y = p2.y + bv[5];
        o1.z = p3.x + bv[6]; o1.w = p3.y + bv[7];
        *(float4*)cp       = o0;
        *(float4*)(cp + 4) = o1;
    }
}

// ---------------------------------------------------------------------------
// Persistent encoder layer, W-resident smem, gate-interleaved.
// grid = (8 j-tiles, 8 b-tiles, 2 dirs) = 128 blocks, 256 threads.
// Per step: h-tile load + 1 __syncthreads + 256 barrier-free k-iters
// (1 LDS.128 w + 1 LDS.128 h + 4 pk2 + 8 FMA2 per kk) + epilogue with
// register-resident c + next-step xg prefetch + PER-DIR grid barrier (64).
// ---------------------------------------------------------------------------
__global__ __launch_bounds__(256) void enc_layer_kernel(
    const float* __restrict__ xg,     // [2][T][B][G]
    const float* __restrict__ whh,    // [2][G][H]
    float* __restrict__ h,            // [2(parity)][2(dir)][B][H]
    float* __restrict__ xout)         // [T][B][512]
{
    const int dir = blockIdx.z;
    const int j0  = blockIdx.x * 32;
    const int b0  = blockIdx.y * 32;
    const int tid = threadIdx.x;
    const int gtid = (((blockIdx.z * gridDim.y + blockIdx.y) * gridDim.x)
                      + blockIdx.x) * 256 + tid;                 // 0..32767

    extern __shared__ float smem_dyn[];
    float (*WsI)[ENC_WS] = (float(*)[ENC_WS])smem_dyn;                // [256][132]
    float (*Hs)[ENC_HS]  = (float(*)[ENC_HS])(smem_dyn + 256 * ENC_WS);// [256][36]

    const float* W = whh + (size_t)dir * GG * HH;

    const int jl = tid & 31;
    const int bq = tid >> 5;        // 0..7 (warp-uniform)
    const int jr = tid >> 3;        // 0..31
    const int kq = tid & 7;         // 0..7
    const int j  = j0 + jl;

    // ---- fused init: zero h(parity 0); c lives in registers ----
    {
        float4 z = make_float4(0.f, 0.f, 0.f, 0.f);
        *(float4*)(h + (size_t)gtid * 4) = z;    // 32768*4 = 2*BB*HH
    }

    // ---- one-time W preload, gate-interleaved:
    //      WsI[k][jr*4 + gt] = W[(gt*HH + j0 + jr)*HH + k] ----
#pragma unroll
    for (int gt = 0; gt < 4; gt++) {
        const float* wrow = W + (size_t)(gt * HH + j0 + jr) * HH;
#pragma unroll
        for (int kc = 0; kc < HH; kc += 32) {
            float4 v = *(const float4*)(wrow + kc + kq * 4);
            int k = kc + kq * 4;
            WsI[k + 0][jr * 4 + gt] = v.x;
            WsI[k + 1][jr * 4 + gt] = v.y;
            WsI[k + 2][jr * 4 + gt] = v.z;
            WsI[k + 3][jr * 4 + gt] = v.w;
        }
    }
    grid_barrier(128);   // full grid once: h zeros visible; W stores synced

    float creg[4] = {0.f, 0.f, 0.f, 0.f};   // register-resident cell state

    // ---- prefetch step-0 xg ----
    float xgv[4][4];   // [gate][bi]
    {
        const int t0 = dir ? (TT - 1) : 0;
        const float* xgp = xg + ((size_t)dir * TT + t0) * (size_t)BB * GG;
#pragma unroll
        for (int bi = 0; bi < 4; bi++) {
            size_t gbase = (size_t)(b0 + bq * 4 + bi) * GG + j;
#pragma unroll
            for (int g = 0; g < 4; g++) xgv[g][bi] = xgp[gbase + g * HH];
        }
    }

#pragma unroll 1
    for (int s = 0; s < TT; s++) {
        const int t = dir ? (TT - 1 - s) : s;
        const float* hi = h + (size_t)(s & 1) * 2 * BB * HH + (size_t)dir * BB * HH;
        float*       ho = h + (size_t)((s + 1) & 1) * 2 * BB * HH + (size_t)dir * BB * HH;

        // ---- cooperative h tile load: Hs[k][b] ----
#pragma unroll
        for (int kc = 0; kc < HH; kc += 32) {
            float4 hv = *(const float4*)(hi + (size_t)(b0 + jr) * HH + kc + kq * 4);
            int k = kc + kq * 4;
            Hs[k + 0][jr] = hv.x; Hs[k + 1][jr] = hv.y;
            Hs[k + 2][jr] = hv.z; Hs[k + 3][jr] = hv.w;
        }
        __syncthreads();

        u64 acc2[4][2];
#pragma unroll
        for (int g = 0; g < 4; g++) { acc2[g][0] = 0ull; acc2[g][1] = 0ull; }

        // ---- barrier-free inner loop: 14 issues per kk for 16 FMAs ----
#pragma unroll 8
        for (int kk = 0; kk < HH; kk++) {
            ulonglong2 hp = *(const ulonglong2*)&Hs[kk][bq * 4];
            float4 wv = *(const float4*)&WsI[kk][jl * 4];
            u64 w0 = pk2(wv.x, wv.x);
            u64 w1 = pk2(wv.y, wv.y);
            u64 w2 = pk2(wv.z, wv.z);
            u64 w3 = pk2(wv.w, wv.w);
            fma2(acc2[0][0], w0, hp.x); fma2(acc2[0][1], w0, hp.y);
            fma2(acc2[1][0], w1, hp.x); fma2(acc2[1][1], w1, hp.y);
            fma2(acc2[2][0], w2, hp.x); fma2(acc2[2][1], w2, hp.y);
            fma2(acc2[3][0], w3, hp.x); fma2(acc2[3][1], w3, hp.y);
        }

        float acc[4][4];
#pragma unroll
        for (int g = 0; g < 4; g++) {
            float2 pa  = upk(acc2[g][0]);
            float2 pbv = upk(acc2[g][1]);
            acc[g][0] = pa.x; acc[g][1] = pa.y; acc[g][2] = pbv.x; acc[g][3] = pbv.y;
        }

#pragma unroll
        for (int bi = 0; bi < 4; bi++) {
            int b = b0 + bq * 4 + bi;
            float gi = acc[0][bi] + xgv[0][bi];
            float gf = acc[1][bi] + xgv[1][bi];
            float gg = acc[2][bi] + xgv[2][bi];
            float go = acc[3][bi] + xgv[3][bi];
            float si = sigf(gi), sf = sigf(gf), so = sigf(go);
            float tg = tanhf(gg);
            float cn = sf * creg[bi] + si * tg;
            creg[bi] = cn;
            float hn = so * tanhf(cn);
            ho[(size_t)b * HH + j] = hn;
            xout[((size_t)t * BB + b) * 512 + dir * HH + j] = hn;
        }

        // ---- prefetch next step's xg BEFORE the barrier ----
        if (s + 1 < TT) {
            const int tn = dir ? (TT - 2 - s) : (s + 1);
            const float* xgp = xg + ((size_t)dir * TT + tn) * (size_t)BB * GG;
#pragma unroll
            for (int bi = 0; bi < 4; bi++) {
                size_t gbase = (size_t)(b0 + bq * 4 + bi) * GG + j;
#pragma unroll
                for (int g = 0; g < 4; g++) xgv[g][bi] = xgp[gbase + g * HH];
            }
        }

        grid_barrier_slot(64, dir * 32);   // only this direction's 64 blocks
    }
}

// ---------------------------------------------------------------------------
// Decoder LSTM cell body (inlined into the persistent decoder kernel).
// Per thread: 4 gates x 2 batch (batch pair packed as f32x2).
// ---------------------------------------------------------------------------
__device__ __forceinline__ void dec_cell_body(
    const float* __restrict__ xin, int Kx,
    const float* __restrict__ wih,
    const float* __restrict__ whh,
    const float* __restrict__ bias,
    const float* __restrict__ h_in,
    float* __restrict__ h_out,
    float* __restrict__ c,
    int j0, int b0, int tid,
    float (*Ws)[129], float (*Xs)[18])
{
    const int jl  = tid & 31;
    const int bq  = tid >> 5;
    const int jr  = tid >> 3;
    const int kq  = tid & 7;
    const int xb  = tid >> 4;
    const int xk2 = (tid & 15) * 2;

    u64 acc2[4];
#pragma unroll
    for (int g = 0; g < 4; g++) acc2[g] = 0ull;

    const float* Wp = wih;
    const float* Xp = xin;
    int Klen = Kx;

#pragma unroll 1
    for (int phase = 0; phase < 2; phase++) {
#pragma unroll 1
        for (int kc = 0; kc < Klen; kc += 32) {
            __syncthreads();
            {
                float2 v = *(const float2*)(Xp + (size_t)(b0 + xb) * Klen + kc + xk2);
                Xs[xk2 + 0][xb] = v.x;
                Xs[xk2 + 1][xb] = v.y;
            }
#pragma unroll
            for (int gt = 0; gt < 4; gt++) {
                int grow = gt * HH + j0 + jr;
                float4 v = *(const float4*)(Wp + (size_t)grow * Klen + kc + kq * 4);
                Ws[kq * 4 + 0][gt * 32 + jr] = v.x; Ws[kq * 4 + 1][gt * 32 + jr] = v.y;
                Ws[kq * 4 + 2][gt * 32 + jr] = v.z; Ws[kq * 4 + 3][gt * 32 + jr] = v.w;
            }
            __syncthreads();
#pragma unroll
            for (int kk = 0; kk < 32; kk++) {
                u64 xp = *(const u64*)&Xs[kk][bq * 2];
                u64 w0 = pk2(Ws[kk][jl],      Ws[kk][jl]);
                u64 w1 = pk2(Ws[kk][32 + jl], Ws[kk][32 + jl]);
                u64 w2 = pk2(Ws[kk][64 + jl], Ws[kk][64 + jl]);
                u64 w3 = pk2(Ws[kk][96 + jl], Ws[kk][96 + jl]);
                fma2(acc2[0], w0, xp);
                fma2(acc2[1], w1, xp);
                fma2(acc2[2], w2, xp);
                fma2(acc2[3], w3, xp);
            }
        }
        Wp = whh; Xp = h_in; Klen = HH;
    }

    float acc[4][2];
#pragma unroll
    for (int g = 0; g < 4; g++) {
        float2 p = upk(acc2[g]);
        acc[g][0] = p.x; acc[g][1] = p.y;
    }

    const int j = j0 + jl;
#pragma unroll
    for (int bi = 0; bi < 2; bi++) {
        int b = b0 + bq * 2 + bi;
        float gi = acc[0][bi] + bias[j];
        float gf = acc[1][bi] + bias[HH + j];
        float gg = acc[2][bi] + bias[2 * HH + j];
        float go = acc[3][bi] + bias[3 * HH + j];
        float si = sigf(gi), sf = sigf(gf), so = sigf(go);
        float tg = tanhf(gg);
        size_t cidx = (size_t)b * HH + j;
        float cn = sf * c[cidx] + si * tg;
        c[cidx] = cn;
        h_out[cidx] = so * tanhf(cn);
    }
}

// ---------------------------------------------------------------------------
// Persistent decoder: init (inp copy + zeros) + all steps in ONE launch.
// 128 blocks, 256 threads. Per step: 3 cells (grid barrier after each) +
// proj/argmax/embed (2 batch rows per block) + end-of-step grid barrier.
// ---------------------------------------------------------------------------
__global__ __launch_bounds__(256) void dec_loop_kernel(
    int steps,
    const float* __restrict__ enc0,    // enc_out base (t=0 slice = first B*512)
    const float* __restrict__ dwih0,   // [1024][512]
    const float* __restrict__ dwihR,   // [2][1024][256]
    const float* __restrict__ dwhh,    // [3][1024][256]
    const float* __restrict__ db,      // [3][1024]
    const float* __restrict__ pw,      // [256][256]
    const float* __restrict__ pb,      // [256]
    const float* __restrict__ emb,     // [256][256]
    float* __restrict__ dh,            // [2][3][B][H]
    float* __restrict__ dc,            // [3][B][H]
    float* __restrict__ inp,           // [B][512]
    float* __restrict__ out)           // [B][steps][256]
{
    const int bid = blockIdx.x;        // 0..127
    const int tid = threadIdx.x;
    const int j0  = (bid & 7) * 32;
    const int b0  = (bid >> 3) * 16;
    const unsigned int nb = gridDim.x; // 128
    const int gtid = bid * 256 + tid;  // 0..32767

    // ---- fused init: inp = enc_out[:,0,:], zero dh(parity0) + dc ----
    {
        *(float4*)(inp + (size_t)gtid * 4) =
            *(const float4*)(enc0 + (size_t)gtid * 4);   // 32768*4 = B*512
#pragma unroll
        for (int rep = 0; rep < 2; rep++) {              // covers 3*BB*HH each
            size_t off = (size_t)(rep * 32768 + gtid) * 3;
            dh[off] = 0.f; dh[off + 1] = 0.f; dh[off + 2] = 0.f;
            dc[off] = 0.f; dc[off + 1] = 0.f; dc[off + 2] = 0.f;
        }
    }
    grid_barrier(nb);

    __shared__ alignas(16) float Ws[32][129];
    __shared__ alignas(16) float Xs[32][18];
    __shared__ alignas(16) float hsh[256];
    __shared__ float sval[256];
    __shared__ int   sidx[256];
    __shared__ int   amax;

#pragma unroll 1
    for (int s = 0; s < steps; s++) {
        const int pr = s & 1;
        float* h_r = dh + (size_t)pr       * 3 * BB * HH;
        float* h_w = dh + (size_t)(1 - pr) * 3 * BB * HH;

#pragma unroll 1
        for (int l = 0; l < 3; l++) {
            const float* wih = (l == 0) ? dwih0 : dwihR + (size_t)(l - 1) * GG * HH;
            const int    Kx  = (l == 0) ? 512 : HH;
            const float* xin = (l == 0) ? inp : h_w + (size_t)(l - 1) * BB * HH;
            dec_cell_body(xin, Kx, wih,
                          dwhh + (size_t)l * GG * HH, db + l * GG,
                          h_r + (size_t)l * BB * HH,
                          h_w + (size_t)l * BB * HH,
                          dc  + (size_t)l * BB * HH,
                          j0, b0, tid, Ws, Xs);
            grid_barrier(nb);
        }

        // proj + argmax (first-index ties) + embedding feedback, 2 rows/block
        const float* h3 = h_w + (size_t)2 * BB * HH;
        const int v = tid;
#pragma unroll 1
        for (int r = 0; r < 2; r++) {
            const int b = bid * 2 + r;
            __syncthreads();
            hsh[v] = h3[(size_t)b * HH + v];
            __syncthreads();

            u64 a2 = 0ull;
            const u64* hp = (const u64*)hsh;
            const u64* wp = (const u64*)(pw + (size_t)v * HH);
#pragma unroll 8
            for (int k2 = 0; k2 < HH / 2; k2++) fma2(a2, hp[k2], wp[k2]);
            float2 ps = upk(a2);
            float acc = pb[v] + ps.x + ps.y;

            out[((size_t)b * steps + s) * 256 + v] = acc;

            sval[v] = acc;
            sidx[v] = v;
            __syncthreads();
#pragma unroll
            for (int off = 128; off >= 1; off >>= 1) {
                if (v < off) {
                    if (sval[v + off] > sval[v]) {   // strict > keeps lower index
                        sval[v] = sval[v + off];
                        sidx[v] = sidx[v + off];
                    }
                }
                __syncthreads();
            }
            if (v == 0) amax = sidx[0];
            __syncthreads();

            inp[(size_t)b * 512 + v]       = emb[(size_t)amax * HH + v];
            inp[(size_t)b * 512 + 256 + v] = 0.f;
        }
        grid_barrier(nb);   // inp/h_w visible before next step's layer 0
    }
}

// ---------------------------------------------------------------------------
// Host driver — 9 graph nodes: noop, embed, (gemm, enc)x3, dec.
// ncu -s 5 -c 1 lands on enc_layer_kernel (layer 1).
// ---------------------------------------------------------------------------
extern "C" void kernel_launch(void* const* d_in, const int* in_sizes, int n_in,
                              void* d_out, int out_size) {
    const int*   text  = (const int*)  d_in[0];
    // d_in[1] = max_nefs_len (steps derived from out_size instead)
    const float* emb   = (const float*)d_in[2];
    const float* ewih0 = (const float*)d_in[3];   // [2][1024][256]
    const float* ewhh0 = (const float*)d_in[4];   // [2][1024][256]
    const float* eb0   = (const float*)d_in[5];   // [2][1024]
    const float* ewihR = (const float*)d_in[6];   // [2][2][1024][512]
    const float* ewhhR = (const float*)d_in[7];   // [2][2][1024][256]
    const float* ebR   = (const float*)d_in[8];   // [2][2][1024]
    const float* dwih0 = (const float*)d_in[9];   // [1024][512]
    const float* dwihR = (const float*)d_in[10];  // [2][1024][256]
    const float* dwhh  = (const float*)d_in[11];  // [3][1024][256]
    const float* db    = (const float*)d_in[12];  // [3][1024]
    const float* pw    = (const float*)d_in[13];  // [256][256]
    const float* pb    = (const float*)d_in[14];  // [256]
    float* out = (float*)d_out;

    const int steps = out_size / (BB * 256);      // = 100

    float *x0, *x1, *xg, *h, *dh, *dc, *inp;
    cudaGetSymbolAddress((void**)&x0,  g_x0);
    cudaGetSymbolAddress((void**)&x1,  g_x1);
    cudaGetSymbolAddress((void**)&xg,  g_xg);
    cudaGetSymbolAddress((void**)&h,   g_h);
    cudaGetSymbolAddress((void**)&dh,  g_dh);
    cudaGetSymbolAddress((void**)&dc,  g_dc);
    cudaGetSymbolAddress((void**)&inp, g_inp);

    // Enable 168KB dynamic smem for the encoder (idempotent; not a stream op)
    cudaFuncSetAttribute(enc_layer_kernel,
                         cudaFuncAttributeMaxDynamicSharedMemorySize,
                         ENC_SMEM_BYTES);

    // 0. Launch-index shim for ncu
    noop_kernel<<<1, 1>>>();

    // 1. Embedding
    embed_kernel<<<(TT * BB) / 4, 256>>>(text, emb, x0);

    // 2. Encoder: 3 bidirectional layers (persistent, self-initializing)
    float* xin   = x0;
    float* xnext = x1;
    for (int l = 0; l < 3; l++) {
        const float* wih; const float* whh; const float* bb; int K;
        if (l == 0) { wih = ewih0; whh = ewhh0; bb = eb0; K = 256; }
        else {
            wih = ewihR + (size_t)(l - 1) * 2 * GG * 512;
            whh = ewhhR + (size_t)(l - 1) * 2 * GG * HH;
            bb  = ebR   + (size_t)(l - 1) * 2 * GG;
            K = 512;
        }
        gemm_xg_kernel<<<dim3((TT * BB) / 128, GG / 128, 2), 256>>>(xin, wih, bb, xg, K);
        enc_layer_kernel<<<dim3(8, 8, 2), 256, ENC_SMEM_BYTES>>>(xg, whh, h, xnext);
        float* tmp = xin; xin = xnext; xnext = tmp;
    }
    // xin now holds enc_out, time-major [T][B][512]

    // 3. Decoder (persistent, self-initializing)
    dec_loop_kernel<<<128, 256>>>(steps, xin, dwih0, dwihR, dwhh, db, pw, pb,
                                  emb, dh, dc, inp, out);
}